// round 14
// baseline (speedup 1.0000x reference)
#include <cuda_runtime.h>
#include <cuda_fp16.h>
#include <cstdint>

#define Bb 2
#define Ss 2048
#define Dd 1024
#define Hh 16
#define HD 64
#define Mtot (Bb*Ss)   // 4096
#define QSCALE 0.1803368801111244f   // 0.125 * log2(e): softmax in exp2 domain

// ---------------- scratch (static device arrays; alloc APIs forbidden) -----
__device__ __align__(16) __half g_qh[Bb*Hh*Ss*HD];  // q split hi/lo (B,H,S,hd)
__device__ __align__(16) __half g_ql[Bb*Hh*Ss*HD];
__device__ __align__(16) __half g_kh[Bb*Hh*Ss*HD];  // k single fp16
__device__ __align__(16) __half g_vh[Bb*Hh*Ss*HD];  // v single fp16
__device__ __align__(16) __half g_xh[Mtot*Dd];      // x split hi/lo
__device__ __align__(16) __half g_xl[Mtot*Dd];
__device__ __align__(16) __half g_w [4u*Dd*Dd];     // Wq,Wk,Wv,Wo single fp16
__device__ __align__(16) __half g_c16[Mtot*Dd];     // ctx single fp16 (B,S,D)

// ---------------- PTX helpers (sm_80/75-era only) --------------------------
__device__ __forceinline__ uint32_t smem_to_u32(const void* p) {
    uint32_t a;
    asm("{ .reg .u64 t; cvta.to.shared.u64 t, %1; cvt.u32.u64 %0, t; }"
        : "=r"(a) : "l"(p));
    return a;
}
__device__ __forceinline__ void cp_async16(uint32_t dst, const void* src) {
    asm volatile("cp.async.cg.shared.global [%0], [%1], 16;"
                 :: "r"(dst), "l"(src) : "memory");
}
__device__ __forceinline__ void cp_commit() {
    asm volatile("cp.async.commit_group;" ::: "memory");
}
template<int N> __device__ __forceinline__ void cp_wait() {
    asm volatile("cp.async.wait_group %0;" :: "n"(N) : "memory");
}
__device__ __forceinline__ void ldsm_x4(uint32_t* r, uint32_t addr) {
    asm volatile("ldmatrix.sync.aligned.m8n8.x4.shared.b16 {%0,%1,%2,%3}, [%4];"
                 : "=r"(r[0]), "=r"(r[1]), "=r"(r[2]), "=r"(r[3]) : "r"(addr));
}
__device__ __forceinline__ void ldsm_x4_t(uint32_t* r, uint32_t addr) {
    asm volatile("ldmatrix.sync.aligned.m8n8.x4.trans.shared.b16 {%0,%1,%2,%3}, [%4];"
                 : "=r"(r[0]), "=r"(r[1]), "=r"(r[2]), "=r"(r[3]) : "r"(addr));
}
__device__ __forceinline__ void mma16816(float* c, const uint32_t* a, const uint32_t* b) {
    asm volatile("mma.sync.aligned.m16n8k16.row.col.f32.f16.f16.f32 "
                 "{%0,%1,%2,%3}, {%4,%5,%6,%7}, {%8,%9}, {%0,%1,%2,%3};"
                 : "+f"(c[0]), "+f"(c[1]), "+f"(c[2]), "+f"(c[3])
                 : "r"(a[0]), "r"(a[1]), "r"(a[2]), "r"(a[3]), "r"(b[0]), "r"(b[1]));
}
__device__ __forceinline__ float ex2(float x) {
    float y;
    asm("ex2.approx.ftz.f32 %0, %1;" : "=f"(y) : "f"(x));
    return y;
}

// ---------------- fp32 -> fp16 hi/lo split ---------------------------------
__device__ __forceinline__ void split2h(float v, __half& h, __half& l) {
    h = __float2half(v);
    l = __float2half(v - __half2float(h));
}
__device__ __forceinline__ uint32_t packh(float a, float b) {
    __half2 t = __floats2half2_rn(a, b);
    return *(uint32_t*)&t;
}

// Split x (hi/lo) + round weights. 4 independent float4 per thread (MLP=4).
__global__ __launch_bounds__(256)
void split_all(const float* __restrict__ x,  const float* __restrict__ Wq,
               const float* __restrict__ Wk, const float* __restrict__ Wv,
               const float* __restrict__ Wo)
{
#pragma unroll
    for (int p = 0; p < 4; p++) {
        int i = blockIdx.x * 4096 + p * 1024 + threadIdx.x * 4;
        if (i < Mtot * Dd) {
            float4 v = *(const float4*)(x + i);
            __half h0, h1, h2, h3, l0, l1, l2, l3;
            split2h(v.x, h0, l0); split2h(v.y, h1, l1);
            split2h(v.z, h2, l2); split2h(v.w, h3, l3);
            *(__half2*)(g_xh + i)     = __half2(h0, h1);
            *(__half2*)(g_xh + i + 2) = __half2(h2, h3);
            *(__half2*)(g_xl + i)     = __half2(l0, l1);
            *(__half2*)(g_xl + i + 2) = __half2(l2, l3);
        } else {
            int j = i - Mtot * Dd;
            int w = j >> 20;                 // Dd*Dd = 2^20
            int r = j & (Dd * Dd - 1);
            const float* src = (w == 0 ? Wq : w == 1 ? Wk : w == 2 ? Wv : Wo) + r;
            float4 v = *(const float4*)src;
            *(__half2*)(g_w + j)     = __floats2half2_rn(v.x, v.y);
            *(__half2*)(g_w + j + 2) = __floats2half2_rn(v.z, v.w);
        }
    }
}

// ---------------------------------------------------------------------------
// Tile geometry: K-chunk 32, smem rows 80B (64B data + 16B pad).
// ---------------------------------------------------------------------------
#define TILE_B    10240                // 128 rows * 80 B
#define TILE64_B  5120                 // 64 rows * 80 B
#define QSTAGE_B  (3 * TILE_B)         // Q stage: xh, xl, Wq(128 rows)
#define KVSTAGE_B (TILE_B + 2 * TILE64_B)  // KV stage: xh + Wk64 + Wv64 = 20480
#define QKV_SMEM  (2 * QSTAGE_B + 512)     // 61952 (covers both paths)
#define OSTAGE_B  (TILE_B + TILE64_B)      // out stage: c16 + Wo64 = 15360
#define OUT_SMEM  (2 * OSTAGE_B + 256)     // 30976

// ---------------------------------------------------------------------------
// Fused projections. grid (16, 32, 2):
//  z=0 (bx<8): Q = (xh+xl)@Wq, 128x128 tile, 2-term, out hi/lo + QSCALE.
//  z=1:        K,V fused: share the A tile; 128x64 tile each of K and V.
// 128 threads, 4 warps (2x2).
// ---------------------------------------------------------------------------
__global__ __launch_bounds__(128)
void gemm_qkv(const float* __restrict__ bq, const float* __restrict__ bk,
              const float* __restrict__ bv)
{
    extern __shared__ char smem[];
    const uint32_t sb = smem_to_u32(smem);
    const int tid = threadIdx.x, wid = tid >> 5, lid = tid & 31;
    const int wm = wid >> 1, wn = wid & 1;
    const int m0 = blockIdx.y * 128;

    const int arow0 = wm * 64 + (lid & 15);
    const int abyte0 = (lid >> 4) * 16;

    if (blockIdx.z == 0) {
        // ================= Q path: 128x128, 2-term =================
        if (blockIdx.x >= 8) return;
        const int n0 = blockIdx.x * 128;
        float* biasS = (float*)(smem + 2 * QSTAGE_B);
        const __half* W16 = g_w;   // Wq
        biasS[tid] = bq[n0 + tid];

        float acc[4][8][4];
#pragma unroll
        for (int i = 0; i < 4; i++)
#pragma unroll
            for (int j = 0; j < 8; j++)
#pragma unroll
                for (int k = 0; k < 4; k++) acc[i][j][k] = 0.f;

        auto issue = [&](int kt, int st) {
            const int kc = kt * 32;
#pragma unroll
            for (int i = 0; i < 12; i++) {
                int idx = tid + i * 128;
                int tile = idx >> 9, w = idx & 511;
                int r = w >> 2, seg = (w & 3) * 16;
                uint32_t dst = sb + st * QSTAGE_B + tile * TILE_B + r * 80 + seg;
                const char* src;
                if (tile == 0)      src = (const char*)(g_xh + (size_t)(m0 + r) * Dd + kc) + seg;
                else if (tile == 1) src = (const char*)(g_xl + (size_t)(m0 + r) * Dd + kc) + seg;
                else                src = (const char*)(W16 + (size_t)(n0 + r) * Dd + kc) + seg;
                cp_async16(dst, src);
            }
            cp_commit();
        };

        issue(0, 0);
        const int brow0 = wn * 64 + ((lid >> 4) << 3) + (lid & 7);
        const int bbyte0 = ((lid >> 3) & 1) * 16;

        int buf = 0;
        for (int kt = 0; kt < 32; kt++) {
            cp_wait<0>();
            __syncthreads();
            if (kt + 1 < 32) issue(kt + 1, buf ^ 1);

            const uint32_t tAh = sb + buf * QSTAGE_B;
            const uint32_t tAl = tAh + TILE_B;
            const uint32_t tBh = tAh + 2 * TILE_B;

#pragma unroll
            for (int kk = 0; kk < 2; kk++) {
                const int ab = kk * 32 + abyte0;
                const int bb = kk * 32 + bbyte0;
                uint32_t aH[4][4], bH[8][2];
#pragma unroll
                for (int mf = 0; mf < 4; mf++)
                    ldsm_x4(aH[mf], tAh + (arow0 + mf * 16) * 80 + ab);
#pragma unroll
                for (int nf2 = 0; nf2 < 4; nf2++) {
                    uint32_t r4[4];
                    ldsm_x4(r4, tBh + (brow0 + nf2 * 16) * 80 + bb);
                    bH[nf2 * 2][0] = r4[0]; bH[nf2 * 2][1] = r4[1];
                    bH[nf2 * 2 + 1][0] = r4[2]; bH[nf2 * 2 + 1][1] = r4[3];
                }
#pragma unroll
                for (int mf = 0; mf < 4; mf++)
#pragma unroll
                    for (int nf = 0; nf < 8; nf++)
                        mma16816(acc[mf][nf], aH[mf], bH[nf]);
                uint32_t aL[4][4];
#pragma unroll
                for (int mf = 0; mf < 4; mf++)
                    ldsm_x4(aL[mf], tAl + (arow0 + mf * 16) * 80 + ab);
#pragma unroll
                for (int mf = 0; mf < 4; mf++)
#pragma unroll
                    for (int nf = 0; nf < 8; nf++)
                        mma16816(acc[mf][nf], aL[mf], bH[nf]);
            }
            buf ^= 1;
        }

#pragma unroll
        for (int mf = 0; mf < 4; mf++) {
#pragma unroll
            for (int nf = 0; nf < 8; nf++) {
                int nl = wn * 64 + nf * 8 + (lid & 3) * 2;
                int n = n0 + nl;
                float b0 = biasS[nl], b1 = biasS[nl + 1];
#pragma unroll
                for (int half = 0; half < 2; half++) {
                    int m = m0 + wm * 64 + mf * 16 + (lid >> 2) + half * 8;
                    float v0 = (acc[mf][nf][half * 2 + 0] + b0) * QSCALE;
                    float v1 = (acc[mf][nf][half * 2 + 1] + b1) * QSCALE;
                    __half h0, l0, h1, l1;
                    split2h(v0, h0, l0); split2h(v1, h1, l1);
                    int b = m >> 11, s = m & (Ss - 1);
                    int hh = n >> 6, d = n & (HD - 1);
                    size_t o = (((size_t)(b * Hh + hh)) * Ss + s) * HD + d;
                    *(__half2*)(g_qh + o) = __half2(h0, h1);
                    *(__half2*)(g_ql + o) = __half2(l0, l1);
                }
            }
        }
    } else {
        // ================= KV fused path: 128x64 each, shared A ==========
        const int n0 = blockIdx.x * 64;
        float* biasKS = (float*)(smem + 2 * KVSTAGE_B);
        float* biasVS = biasKS + 64;
        const __half* Wk16 = g_w + (size_t)1 * Dd * Dd;
        const __half* Wv16 = g_w + (size_t)2 * Dd * Dd;
        if (tid < 64) biasKS[tid] = bk[n0 + tid];
        else          biasVS[tid - 64] = bv[n0 + tid - 64];

        float accK[4][4][4], accV[4][4][4];
#pragma unroll
        for (int i = 0; i < 4; i++)
#pragma unroll
            for (int j = 0; j < 4; j++)
#pragma unroll
                for (int k = 0; k < 4; k++) { accK[i][j][k] = 0.f; accV[i][j][k] = 0.f; }

        auto issue = [&](int kt, int st) {
            const int kc = kt * 32;
#pragma unroll
            for (int i = 0; i < 8; i++) {
                int idx = tid + i * 128;   // 1024 chunks: 512 xh, 256 Wk, 256 Wv
                const char* src;
                uint32_t dst;
                if (idx < 512) {
                    int r = idx >> 2, seg = (idx & 3) * 16;
                    src = (const char*)(g_xh + (size_t)(m0 + r) * Dd + kc) + seg;
                    dst = sb + st * KVSTAGE_B + r * 80 + seg;
                } else if (idx < 768) {
                    int w = idx - 512;
                    int r = w >> 2, seg = (w & 3) * 16;
                    src = (const char*)(Wk16 + (size_t)(n0 + r) * Dd + kc) + seg;
                    dst = sb + st * KVSTAGE_B + TILE_B + r * 80 + seg;
                } else {
                    int w = idx - 768;
                    int r = w >> 2, seg = (w & 3) * 16;
                    src = (const char*)(Wv16 + (size_t)(n0 + r) * Dd + kc) + seg;
                    dst = sb + st * KVSTAGE_B + TILE_B + TILE64_B + r * 80 + seg;
                }
                cp_async16(dst, src);
            }
            cp_commit();
        };

        issue(0, 0);
        const int brow0 = wn * 32 + ((lid >> 4) << 3) + (lid & 7);
        const int bbyte0 = ((lid >> 3) & 1) * 16;

        int buf = 0;
        for (int kt = 0; kt < 32; kt++) {
            cp_wait<0>();
            __syncthreads();
            if (kt + 1 < 32) issue(kt + 1, buf ^ 1);

            const uint32_t tA  = sb + buf * KVSTAGE_B;
            const uint32_t tBk = tA + TILE_B;
            const uint32_t tBv = tBk + TILE64_B;

#pragma unroll
            for (int kk = 0; kk < 2; kk++) {
                const int ab = kk * 32 + abyte0;
                const int bb = kk * 32 + bbyte0;
                uint32_t aH[4][4], bK[4][2], bV[4][2];
#pragma unroll
                for (int mf = 0; mf < 4; mf++)
                    ldsm_x4(aH[mf], tA + (arow0 + mf * 16) * 80 + ab);
#pragma unroll
                for (int nf2 = 0; nf2 < 2; nf2++) {
                    uint32_t r4[4];
                    ldsm_x4(r4, tBk + (brow0 + nf2 * 16) * 80 + bb);
                    bK[nf2 * 2][0] = r4[0]; bK[nf2 * 2][1] = r4[1];
                    bK[nf2 * 2 + 1][0] = r4[2]; bK[nf2 * 2 + 1][1] = r4[3];
                    ldsm_x4(r4, tBv + (brow0 + nf2 * 16) * 80 + bb);
                    bV[nf2 * 2][0] = r4[0]; bV[nf2 * 2][1] = r4[1];
                    bV[nf2 * 2 + 1][0] = r4[2]; bV[nf2 * 2 + 1][1] = r4[3];
                }
#pragma unroll
                for (int mf = 0; mf < 4; mf++)
#pragma unroll
                    for (int nf = 0; nf < 4; nf++)
                        mma16816(accK[mf][nf], aH[mf], bK[nf]);
#pragma unroll
                for (int mf = 0; mf < 4; mf++)
#pragma unroll
                    for (int nf = 0; nf < 4; nf++)
                        mma16816(accV[mf][nf], aH[mf], bV[nf]);
            }
            buf ^= 1;
        }

#pragma unroll
        for (int mf = 0; mf < 4; mf++) {
#pragma unroll
            for (int nf = 0; nf < 4; nf++) {
                int nl = wn * 32 + nf * 8 + (lid & 3) * 2;
                int n = n0 + nl;
                float bk0 = biasKS[nl], bk1 = biasKS[nl + 1];
                float bv0 = biasVS[nl], bv1 = biasVS[nl + 1];
#pragma unroll
                for (int half = 0; half < 2; half++) {
                    int m = m0 + wm * 64 + mf * 16 + (lid >> 2) + half * 8;
                    int b = m >> 11, s = m & (Ss - 1);
                    int hh = n >> 6, d = n & (HD - 1);
                    size_t o = (((size_t)(b * Hh + hh)) * Ss + s) * HD + d;
                    *(__half2*)(g_kh + o) =
                        __floats2half2_rn(accK[mf][nf][half * 2 + 0] + bk0,
                                          accK[mf][nf][half * 2 + 1] + bk1);
                    *(__half2*)(g_vh + o) =
                        __floats2half2_rn(accV[mf][nf][half * 2 + 0] + bv0,
                                          accV[mf][nf][half * 2 + 1] + bv1);
                }
            }
        }
    }
}

// ---------------------------------------------------------------------------
// Output GEMM: out = c16 @ Wo16^T + bo, fp32. 128x64 tiles, 128 threads.
// ---------------------------------------------------------------------------
__global__ __launch_bounds__(128)
void gemm_out(const float* __restrict__ bias, float* __restrict__ Cout)
{
    extern __shared__ char smem[];
    const uint32_t sb = smem_to_u32(smem);
    float* biasS = (float*)(smem + 2 * OSTAGE_B);

    const int tid = threadIdx.x, wid = tid >> 5, lid = tid & 31;
    const int wm = wid >> 1, wn = wid & 1;
    const int m0 = blockIdx.y * 128, n0 = blockIdx.x * 64;

    const __half* W16 = g_w + (size_t)3 * Dd * Dd;
    if (tid < 64) biasS[tid] = bias[n0 + tid];

    float acc[4][4][4];
#pragma unroll
    for (int i = 0; i < 4; i++)
#pragma unroll
        for (int j = 0; j < 4; j++)
#pragma unroll
            for (int k = 0; k < 4; k++) acc[i][j][k] = 0.f;

    auto issue = [&](int kt, int st) {
        const int kc = kt * 32;
#pragma unroll
        for (int i = 0; i < 6; i++) {
            int idx = tid + i * 128;   // 768 chunks: 512 c16 + 256 Wo
            const char* src;
            uint32_t dst;
            if (idx < 512) {
                int r = idx >> 2, seg = (idx & 3) * 16;
                src = (const char*)(g_c16 + (size_t)(m0 + r) * Dd + kc) + seg;
                dst = sb + st * OSTAGE_B + r * 80 + seg;
            } else {
                int w = idx - 512;
                int r = w >> 2, seg = (w & 3) * 16;
                src = (const char*)(W16 + (size_t)(n0 + r) * Dd + kc) + seg;
                dst = sb + st * OSTAGE_B + TILE_B + r * 80 + seg;
            }
            cp_async16(dst, src);
        }
        cp_commit();
    };

    issue(0, 0);
    const int arow0 = wm * 64 + (lid & 15);
    const int abyte0 = (lid >> 4) * 16;
    const int brow0 = wn * 32 + ((lid >> 4) << 3) + (lid & 7);
    const int bbyte0 = ((lid >> 3) & 1) * 16;

    int buf = 0;
    for (int kt = 0; kt < 32; kt++) {
        cp_wait<0>();
        __syncthreads();
        if (kt + 1 < 32) issue(kt + 1, buf ^ 1);

        const uint32_t tA = sb + buf * OSTAGE_B;
        const uint32_t tB = tA + TILE_B;

#pragma unroll
        for (int kk = 0; kk < 2; kk++) {
            const int ab = kk * 32 + abyte0;
            const int bb = kk * 32 + bbyte0;
            uint32_t aH[4][4], bH[4][2];
#pragma unroll
            for (int mf = 0; mf < 4; mf++)
                ldsm_x4(aH[mf], tA + (arow0 + mf * 16) * 80 + ab);
#pragma unroll
            for (int nf2 = 0; nf2 < 2; nf2++) {
                uint32_t r4[4];
                ldsm_x4(r4, tB + (brow0 + nf2 * 16) * 80 + bb);
                bH[nf2 * 2][0] = r4[0]; bH[nf2 * 2][1] = r4[1];
                bH[nf2 * 2 + 1][0] = r4[2]; bH[nf2 * 2 + 1][1] = r4[3];
            }
#pragma unroll
            for (int mf = 0; mf < 4; mf++)
#pragma unroll
                for (int nf = 0; nf < 4; nf++)
                    mma16816(acc[mf][nf], aH[mf], bH[nf]);
        }
        buf ^= 1;
    }

#pragma unroll
    for (int mf = 0; mf < 4; mf++) {
#pragma unroll
        for (int nf = 0; nf < 4; nf++) {
            int nl = wn * 32 + nf * 8 + (lid & 3) * 2;
            int n = n0 + nl;
            float b0 = biasS[nl], b1 = biasS[nl + 1];
#pragma unroll
            for (int half = 0; half < 2; half++) {
                int m = m0 + wm * 64 + mf * 16 + (lid >> 2) + half * 8;
                *(float2*)(Cout + (size_t)m * Dd + n) =
                    make_float2(acc[mf][nf][half * 2 + 0] + b0,
                                acc[mf][nf][half * 2 + 1] + b1);
            }
        }
    }
}

// ---------------------------------------------------------------------------
// Tensor-core causal flash attention. S = (qh+ql)@k16 (2 terms);
// O += P16@v16 (1 term). KV ring 3-stage. q-tile 128 rows, 256 thr / 8 warps.
// ---------------------------------------------------------------------------
#define AT_STRIDE 144
#define QT_B     (128 * AT_STRIDE)           // 18432
#define KV_TILE  (64 * AT_STRIDE)            // 9216
#define KV0      (2 * QT_B)                  // 36864
#define KV_STAGE (2 * KV_TILE)               // 18432 (k + v)
#define ATTN_SMEM (KV0 + 3 * KV_STAGE)       // 92160

__global__ __launch_bounds__(256, 2)
void attn_mma()
{
    extern __shared__ char smem[];
    const uint32_t sb = smem_to_u32(smem);
    const int pr = blockIdx.x;                 // pair index 0..7
    const int bh = blockIdx.y;
    const int b = bh >> 4, h = bh & 15;
    const int tid = threadIdx.x, wid = tid >> 5, lid = tid & 31;

    const __half* kbase = g_kh + (size_t)bh * Ss * HD;
    const __half* vbase = g_vh + (size_t)bh * Ss * HD;

    auto issue = [&](int kt, int st) {
#pragma unroll
        for (int i = 0; i < 4; i++) {
            int idx = tid + i * 256;
            int t = idx >> 9, w = idx & 511;
            int r = w >> 3, c = w & 7;
            const __half* src = (t ? vbase : kbase) + (size_t)(kt * 64 + r) * HD + c * 8;
            cp_async16(sb + KV0 + st * KV_STAGE + t * KV_TILE + r * AT_STRIDE + c * 16, src);
        }
        cp_commit();
    };

    const uint32_t qrowb = (wid * 16 + (lid & 15)) * AT_STRIDE + (lid >> 4) * 16;
    const uint32_t krowb = (((lid >> 4) << 3) + (lid & 7)) * AT_STRIDE + ((lid >> 3) & 1) * 16;
    const uint32_t vrowb = (lid & 15) * AT_STRIDE + ((lid >> 4) & 1) * 16;

    for (int half_t = 0; half_t < 2; half_t++) {
        const int qt = half_t ? (15 - pr) : pr;       // q-tile of 128 rows
        const __half* QH = g_qh + ((size_t)bh * Ss + qt * 128) * HD;
        const __half* QL = g_ql + ((size_t)bh * Ss + qt * 128) * HD;
        const int nk = 2 * qt + 2;

        // Q tile (qh, ql): 128 rows x 128B each (own commit group)
#pragma unroll
        for (int i = 0; i < 8; i++) {
            int idx = tid + i * 256;
            int s = idx >> 10, w = idx & 1023;
            int r = w >> 3, c = w & 7;
            cp_async16(sb + s * QT_B + r * AT_STRIDE + c * 16,
                       (s ? QL : QH) + (size_t)r * HD + c * 8);
        }
        cp_commit();
        issue(0, 0);
        if (nk > 1) issue(1, 1);

        float acc[8][4];
#pragma unroll
        for (int i = 0; i < 8; i++)
#pragma unroll
            for (int j = 0; j < 4; j++) acc[i][j] = 0.f;
        float mrow[2] = { -1e30f, -1e30f }, lrow[2] = { 0.f, 0.f };

        int stage = 0;
        for (int kt = 0; kt < nk; kt++) {
            if (kt + 1 < nk) cp_wait<1>(); else cp_wait<0>();
            __syncthreads();          // chunk kt (and Q) ready + old stage reads done
            if (kt + 2 < nk) issue(kt + 2, (kt + 2) % 3);

            const uint32_t kbt = sb + KV0 + stage * KV_STAGE;
            const uint32_t vbt = kbt + KV_TILE;

            // ---- S = (qh + ql) @ k16^T  (2 MMA terms) ----
            float sf[8][4];
#pragma unroll
            for (int i = 0; i < 8; i++)
#pragma unroll
                for (int j = 0; j < 4; j++) sf[i][j] = 0.f;

#pragma unroll
            for (int kk = 0; kk < 4; kk++) {
                uint32_t aH[4], aL[4];
                ldsm_x4(aH, sb + qrowb + kk * 32);
                ldsm_x4(aL, sb + QT_B + qrowb + kk * 32);
#pragma unroll
                for (int nf2 = 0; nf2 < 4; nf2++) {
                    uint32_t rH[4];
                    ldsm_x4(rH, kbt + nf2 * 16 * AT_STRIDE + krowb + kk * 32);
                    mma16816(sf[nf2 * 2],     aH, rH);
                    mma16816(sf[nf2 * 2 + 1], aH, rH + 2);
                    mma16816(sf[nf2 * 2],     aL, rH);
                    mma16816(sf[nf2 * 2 + 1], aL, rH + 2);
                }
            }

            if (kt >= 2 * qt) {     // diagonal region: causal mask
                int r0 = wid * 16 + (lid >> 2);
                int coff = kt * 64 - qt * 128;
#pragma unroll
                for (int nf = 0; nf < 8; nf++) {
                    int c0 = coff + nf * 8 + (lid & 3) * 2;
                    if (c0     > r0)     sf[nf][0] = -1e30f;
                    if (c0 + 1 > r0)     sf[nf][1] = -1e30f;
                    if (c0     > r0 + 8) sf[nf][2] = -1e30f;
                    if (c0 + 1 > r0 + 8) sf[nf][3] = -1e30f;
                }
            }

            // ---- online softmax in exp2 domain ----
#pragma unroll
            for (int hf = 0; hf < 2; hf++) {
                float mx = -1e30f;
#pragma unroll
                for (int nf = 0; nf < 8; nf++)
                    mx = fmaxf(mx, fmaxf(sf[nf][hf * 2], sf[nf][hf * 2 + 1]));
                mx = fmaxf(mx, __shfl_xor_sync(0xffffffffu, mx, 1));
                mx = fmaxf(mx, __shfl_xor_sync(0xffffffffu, mx, 2));
                float mnew = fmaxf(mrow[hf], mx);
                float alpha = ex2(mrow[hf] - mnew);
                mrow[hf] = mnew;
                float sum = 0.f;
#pragma unroll
                for (int nf = 0; nf < 8; nf++) {
                    sf[nf][hf * 2]     = ex2(sf[nf][hf * 2] - mnew);
                    sf[nf][hf * 2 + 1] = ex2(sf[nf][hf * 2 + 1] - mnew);
                    sum += sf[nf][hf * 2] + sf[nf][hf * 2 + 1];
                }
                sum += __shfl_xor_sync(0xffffffffu, sum, 1);
                sum += __shfl_xor_sync(0xffffffffu, sum, 2);
                lrow[hf] = lrow[hf] * alpha + sum;
#pragma unroll
                for (int nf = 0; nf < 8; nf++) {
                    acc[nf][hf * 2]     *= alpha;
                    acc[nf][hf * 2 + 1] *= alpha;
                }
            }

            // ---- O += P16 @ v16  (1 MMA term) ----
#pragma unroll
            for (int kk2 = 0; kk2 < 4; kk2++) {
                uint32_t aPh[4];
#pragma unroll
                for (int q = 0; q < 2; q++) {
                    const float* c = sf[kk2 * 2 + q];
                    aPh[q * 2]     = packh(c[0], c[1]);
                    aPh[q * 2 + 1] = packh(c[2], c[3]);
                }
#pragma unroll
                for (int nf2 = 0; nf2 < 4; nf2++) {
                    uint32_t vH[4];
                    ldsm_x4_t(vH, vbt + (kk2 * 16) * AT_STRIDE + vrowb + nf2 * 32);
                    mma16816(acc[nf2 * 2],     aPh, vH);
                    mma16816(acc[nf2 * 2 + 1], aPh, vH + 2);
                }
            }
            stage = (stage == 2) ? 0 : stage + 1;
        }

        // ---- epilogue: ctx -> single fp16 (B,S,D) ----
        float inv0 = 1.f / lrow[0], inv1 = 1.f / lrow[1];
        int r0 = qt * 128 + wid * 16 + (lid >> 2);
#pragma unroll
        for (int nf = 0; nf < 8; nf++) {
            int d0 = h * HD + nf * 8 + (lid & 3) * 2;
            size_t o0 = ((size_t)b * Ss + r0) * Dd + d0;
            size_t o1 = ((size_t)b * Ss + r0 + 8) * Dd + d0;
            *(__half2*)(g_c16 + o0) =
                __floats2half2_rn(acc[nf][0] * inv0, acc[nf][1] * inv0);
            *(__half2*)(g_c16 + o1) =
                __floats2half2_rn(acc[nf][2] * inv1, acc[nf][3] * inv1);
        }
        __syncthreads();    // all smem reads done before next half's loads
    }
}

// ---------------------------------------------------------------------------
extern "C" void kernel_launch(void* const* d_in, const int* in_sizes, int n_in,
                              void* d_out, int out_size)
{
    const float* x  = (const float*)d_in[0];
    const float* Wq = (const float*)d_in[1];
    const float* bq = (const float*)d_in[2];
    const float* Wk = (const float*)d_in[3];
    const float* bk = (const float*)d_in[4];
    const float* Wv = (const float*)d_in[5];
    const float* bv = (const float*)d_in[6];
    const float* Wo = (const float*)d_in[7];
    const float* bo = (const float*)d_in[8];
    float* out = (float*)d_out;

    cudaFuncSetAttribute(gemm_qkv, cudaFuncAttributeMaxDynamicSharedMemorySize, QKV_SMEM);
    cudaFuncSetAttribute(gemm_out, cudaFuncAttributeMaxDynamicSharedMemorySize, OUT_SMEM);
    cudaFuncSetAttribute(attn_mma, cudaFuncAttributeMaxDynamicSharedMemorySize, ATTN_SMEM);

    split_all<<<(Mtot * Dd + 4 * Dd * Dd) / 4096, 256>>>(x, Wq, Wk, Wv, Wo);

    gemm_qkv<<<dim3(16, 32, 2), 128, QKV_SMEM>>>(bq, bk, bv);

    attn_mma<<<dim3(8, Bb * Hh), 256, ATTN_SMEM>>>();

    gemm_out<<<dim3(16, 32), 128, OUT_SMEM>>>(bo, out);
}

// round 15
// speedup vs baseline: 1.0653x; 1.0653x over previous
#include <cuda_runtime.h>
#include <cuda_fp16.h>
#include <cstdint>

#define Bb 2
#define Ss 2048
#define Dd 1024
#define Hh 16
#define HD 64
#define Mtot (Bb*Ss)   // 4096
#define QSCALE 0.1803368801111244f   // 0.125 * log2(e): softmax in exp2 domain

// ---------------- scratch (static device arrays; alloc APIs forbidden) -----
__device__ __align__(16) __half g_q16[Bb*Hh*Ss*HD]; // q single fp16 (B,H,S,hd)
__device__ __align__(16) __half g_kh[Bb*Hh*Ss*HD];  // k single fp16
__device__ __align__(16) __half g_vh[Bb*Hh*Ss*HD];  // v single fp16
__device__ __align__(16) __half g_xh[Mtot*Dd];      // x split hi/lo
__device__ __align__(16) __half g_xl[Mtot*Dd];
__device__ __align__(16) __half g_w [4u*Dd*Dd];     // Wq,Wk,Wv,Wo single fp16
__device__ __align__(16) __half g_c16[Mtot*Dd];     // ctx single fp16 (B,S,D)

// ---------------- PTX helpers (sm_80/75-era only) --------------------------
__device__ __forceinline__ uint32_t smem_to_u32(const void* p) {
    uint32_t a;
    asm("{ .reg .u64 t; cvta.to.shared.u64 t, %1; cvt.u32.u64 %0, t; }"
        : "=r"(a) : "l"(p));
    return a;
}
__device__ __forceinline__ void cp_async16(uint32_t dst, const void* src) {
    asm volatile("cp.async.cg.shared.global [%0], [%1], 16;"
                 :: "r"(dst), "l"(src) : "memory");
}
__device__ __forceinline__ void cp_commit() {
    asm volatile("cp.async.commit_group;" ::: "memory");
}
template<int N> __device__ __forceinline__ void cp_wait() {
    asm volatile("cp.async.wait_group %0;" :: "n"(N) : "memory");
}
__device__ __forceinline__ void ldsm_x4(uint32_t* r, uint32_t addr) {
    asm volatile("ldmatrix.sync.aligned.m8n8.x4.shared.b16 {%0,%1,%2,%3}, [%4];"
                 : "=r"(r[0]), "=r"(r[1]), "=r"(r[2]), "=r"(r[3]) : "r"(addr));
}
__device__ __forceinline__ void ldsm_x4_t(uint32_t* r, uint32_t addr) {
    asm volatile("ldmatrix.sync.aligned.m8n8.x4.trans.shared.b16 {%0,%1,%2,%3}, [%4];"
                 : "=r"(r[0]), "=r"(r[1]), "=r"(r[2]), "=r"(r[3]) : "r"(addr));
}
__device__ __forceinline__ void mma16816(float* c, const uint32_t* a, const uint32_t* b) {
    asm volatile("mma.sync.aligned.m16n8k16.row.col.f32.f16.f16.f32 "
                 "{%0,%1,%2,%3}, {%4,%5,%6,%7}, {%8,%9}, {%0,%1,%2,%3};"
                 : "+f"(c[0]), "+f"(c[1]), "+f"(c[2]), "+f"(c[3])
                 : "r"(a[0]), "r"(a[1]), "r"(a[2]), "r"(a[3]), "r"(b[0]), "r"(b[1]));
}
__device__ __forceinline__ float ex2(float x) {
    float y;
    asm("ex2.approx.ftz.f32 %0, %1;" : "=f"(y) : "f"(x));
    return y;
}

// ---------------- fp32 -> fp16 hi/lo split ---------------------------------
__device__ __forceinline__ void split2h(float v, __half& h, __half& l) {
    h = __float2half(v);
    l = __float2half(v - __half2float(h));
}
__device__ __forceinline__ uint32_t packh(float a, float b) {
    __half2 t = __floats2half2_rn(a, b);
    return *(uint32_t*)&t;
}

// Split x (hi/lo) + round weights. 4 independent float4 per thread (MLP=4).
__global__ __launch_bounds__(256)
void split_all(const float* __restrict__ x,  const float* __restrict__ Wq,
               const float* __restrict__ Wk, const float* __restrict__ Wv,
               const float* __restrict__ Wo)
{
#pragma unroll
    for (int p = 0; p < 4; p++) {
        int i = blockIdx.x * 4096 + p * 1024 + threadIdx.x * 4;
        if (i < Mtot * Dd) {
            float4 v = *(const float4*)(x + i);
            __half h0, h1, h2, h3, l0, l1, l2, l3;
            split2h(v.x, h0, l0); split2h(v.y, h1, l1);
            split2h(v.z, h2, l2); split2h(v.w, h3, l3);
            *(__half2*)(g_xh + i)     = __half2(h0, h1);
            *(__half2*)(g_xh + i + 2) = __half2(h2, h3);
            *(__half2*)(g_xl + i)     = __half2(l0, l1);
            *(__half2*)(g_xl + i + 2) = __half2(l2, l3);
        } else {
            int j = i - Mtot * Dd;
            int w = j >> 20;                 // Dd*Dd = 2^20
            int r = j & (Dd * Dd - 1);
            const float* src = (w == 0 ? Wq : w == 1 ? Wk : w == 2 ? Wv : Wo) + r;
            float4 v = *(const float4*)src;
            *(__half2*)(g_w + j)     = __floats2half2_rn(v.x, v.y);
            *(__half2*)(g_w + j + 2) = __floats2half2_rn(v.z, v.w);
        }
    }
}

// ---------------------------------------------------------------------------
// mma.sync GEMM cores. Block 128x128, FOUR warps (2x2 grid of 64x64 warp
// tiles), 2-stage cp.async double buffer.
// qkv: Q = (xh+xl)@W (2-term compute, single fp16 store + QSCALE);
//      K/V = xh@W (1 term). out: out = c16@Wo (1 term, fp32 result).
// ---------------------------------------------------------------------------
#define TILE_B   10240                 // 128 rows * 80 B
#define BUF3_B   (3 * TILE_B)          // qkv stage: xh, xl, W
#define QKV_SMEM (2 * BUF3_B + 512)    // 61952
#define BUF2_B   (2 * TILE_B)          // out stage: c16, W
#define OUT_SMEM (2 * BUF2_B + 512)    // 41472

// Fused QKV projection: gridDim.z selects Q(2-term)/K(1-term)/V(1-term).
__global__ __launch_bounds__(128)
void gemm_qkv(const float* __restrict__ bq, const float* __restrict__ bk,
              const float* __restrict__ bv)
{
    extern __shared__ char smem[];
    const uint32_t sb = smem_to_u32(smem);
    float* biasS = (float*)(smem + 2 * BUF3_B);

    const int tid = threadIdx.x, wid = tid >> 5, lid = tid & 31;
    const int wm = wid >> 1, wn = wid & 1;
    const int m0 = blockIdx.y * 128, n0 = blockIdx.x * 128;
    const int z = blockIdx.z;
    const bool doLo = (z == 0);

    const float* bias = (z == 0) ? bq : (z == 1) ? bk : bv;
    const __half* W16 = g_w + (size_t)z * Dd * Dd;

    biasS[tid] = bias[n0 + tid];

    float acc[4][8][4];
#pragma unroll
    for (int i = 0; i < 4; i++)
#pragma unroll
        for (int j = 0; j < 8; j++)
#pragma unroll
            for (int k = 0; k < 4; k++) acc[i][j][k] = 0.f;

    auto issue = [&](int kt, int st) {
        const int kc = kt * 32;
#pragma unroll
        for (int i = 0; i < 12; i++) {
            int idx = tid + i * 128;
            int tile = idx >> 9, w = idx & 511;
            if (tile == 1 && !doLo) continue;      // xl unused for K/V
            int r = w >> 2, seg = (w & 3) * 16;
            uint32_t dst = sb + st * BUF3_B + tile * TILE_B + r * 80 + seg;
            const char* src;
            if (tile == 0)      src = (const char*)(g_xh + (size_t)(m0 + r) * Dd + kc) + seg;
            else if (tile == 1) src = (const char*)(g_xl + (size_t)(m0 + r) * Dd + kc) + seg;
            else                src = (const char*)(W16 + (size_t)(n0 + r) * Dd + kc) + seg;
            cp_async16(dst, src);
        }
        cp_commit();
    };

    issue(0, 0);
    const int arow0 = wm * 64 + (lid & 15);
    const int abyte0 = (lid >> 4) * 16;
    const int brow0 = wn * 64 + ((lid >> 4) << 3) + (lid & 7);
    const int bbyte0 = ((lid >> 3) & 1) * 16;

    int buf = 0;
    for (int kt = 0; kt < 32; kt++) {
        cp_wait<0>();
        __syncthreads();               // data ready + prior reads of buf^1 done
        if (kt + 1 < 32) issue(kt + 1, buf ^ 1);

        const uint32_t tAh = sb + buf * BUF3_B;
        const uint32_t tAl = tAh + TILE_B;
        const uint32_t tBh = tAh + 2 * TILE_B;

#pragma unroll
        for (int kk = 0; kk < 2; kk++) {
            const int ab = kk * 32 + abyte0;
            const int bb = kk * 32 + bbyte0;
            uint32_t aH[4][4], bH[8][2];
#pragma unroll
            for (int mf = 0; mf < 4; mf++)
                ldsm_x4(aH[mf], tAh + (arow0 + mf * 16) * 80 + ab);
#pragma unroll
            for (int nf2 = 0; nf2 < 4; nf2++) {
                uint32_t r4[4];
                ldsm_x4(r4, tBh + (brow0 + nf2 * 16) * 80 + bb);
                bH[nf2 * 2][0] = r4[0]; bH[nf2 * 2][1] = r4[1];
                bH[nf2 * 2 + 1][0] = r4[2]; bH[nf2 * 2 + 1][1] = r4[3];
            }
#pragma unroll
            for (int mf = 0; mf < 4; mf++)
#pragma unroll
                for (int nf = 0; nf < 8; nf++)
                    mma16816(acc[mf][nf], aH[mf], bH[nf]);
            if (doLo) {
                uint32_t aL[4][4];
#pragma unroll
                for (int mf = 0; mf < 4; mf++)
                    ldsm_x4(aL[mf], tAl + (arow0 + mf * 16) * 80 + ab);
#pragma unroll
                for (int mf = 0; mf < 4; mf++)
#pragma unroll
                    for (int nf = 0; nf < 8; nf++)
                        mma16816(acc[mf][nf], aL[mf], bH[nf]);
            }
        }
        buf ^= 1;
    }

    const float scale = (z == 0) ? QSCALE : 1.f;
    __half* dst = (z == 0) ? g_q16 : (z == 1) ? g_kh : g_vh;
#pragma unroll
    for (int mf = 0; mf < 4; mf++) {
#pragma unroll
        for (int nf = 0; nf < 8; nf++) {
            int nl = wn * 64 + nf * 8 + (lid & 3) * 2;
            int n = n0 + nl;
            float b0 = biasS[nl], b1 = biasS[nl + 1];
#pragma unroll
            for (int half = 0; half < 2; half++) {
                int m = m0 + wm * 64 + mf * 16 + (lid >> 2) + half * 8;
                float v0 = (acc[mf][nf][half * 2 + 0] + b0) * scale;
                float v1 = (acc[mf][nf][half * 2 + 1] + b1) * scale;
                int b = m >> 11, s = m & (Ss - 1);
                int hh = n >> 6, d = n & (HD - 1);
                size_t o = (((size_t)(b * Hh + hh)) * Ss + s) * HD + d;
                *(__half2*)(dst + o) = __floats2half2_rn(v0, v1);
            }
        }
    }
}

// Output GEMM: out = c16 @ Wo16^T + bo, fp32 result (1 term).
__global__ __launch_bounds__(128)
void gemm_out(const float* __restrict__ bias, float* __restrict__ Cout)
{
    extern __shared__ char smem[];
    const uint32_t sb = smem_to_u32(smem);
    float* biasS = (float*)(smem + 2 * BUF2_B);

    const int tid = threadIdx.x, wid = tid >> 5, lid = tid & 31;
    const int wm = wid >> 1, wn = wid & 1;
    const int m0 = blockIdx.y * 128, n0 = blockIdx.x * 128;

    const __half* W16 = g_w + (size_t)3 * Dd * Dd;

    biasS[tid] = bias[n0 + tid];

    float acc[4][8][4];
#pragma unroll
    for (int i = 0; i < 4; i++)
#pragma unroll
        for (int j = 0; j < 8; j++)
#pragma unroll
            for (int k = 0; k < 4; k++) acc[i][j][k] = 0.f;

    auto issue = [&](int kt, int st) {
        const int kc = kt * 32;
#pragma unroll
        for (int i = 0; i < 8; i++) {
            int idx = tid + i * 128;
            int tile = idx >> 9, w = idx & 511;
            int r = w >> 2, seg = (w & 3) * 16;
            uint32_t dst = sb + st * BUF2_B + tile * TILE_B + r * 80 + seg;
            const char* src;
            if (tile == 0) src = (const char*)(g_c16 + (size_t)(m0 + r) * Dd + kc) + seg;
            else           src = (const char*)(W16 + (size_t)(n0 + r) * Dd + kc) + seg;
            cp_async16(dst, src);
        }
        cp_commit();
    };

    issue(0, 0);
    const int arow0 = wm * 64 + (lid & 15);
    const int abyte0 = (lid >> 4) * 16;
    const int brow0 = wn * 64 + ((lid >> 4) << 3) + (lid & 7);
    const int bbyte0 = ((lid >> 3) & 1) * 16;

    int buf = 0;
    for (int kt = 0; kt < 32; kt++) {
        cp_wait<0>();
        __syncthreads();
        if (kt + 1 < 32) issue(kt + 1, buf ^ 1);

        const uint32_t tA = sb + buf * BUF2_B;
        const uint32_t tB = tA + TILE_B;

#pragma unroll
        for (int kk = 0; kk < 2; kk++) {
            const int ab = kk * 32 + abyte0;
            const int bb = kk * 32 + bbyte0;
            uint32_t aH[4][4], bH[8][2];
#pragma unroll
            for (int mf = 0; mf < 4; mf++)
                ldsm_x4(aH[mf], tA + (arow0 + mf * 16) * 80 + ab);
#pragma unroll
            for (int nf2 = 0; nf2 < 4; nf2++) {
                uint32_t r4[4];
                ldsm_x4(r4, tB + (brow0 + nf2 * 16) * 80 + bb);
                bH[nf2 * 2][0] = r4[0]; bH[nf2 * 2][1] = r4[1];
                bH[nf2 * 2 + 1][0] = r4[2]; bH[nf2 * 2 + 1][1] = r4[3];
            }
#pragma unroll
            for (int mf = 0; mf < 4; mf++)
#pragma unroll
                for (int nf = 0; nf < 8; nf++)
                    mma16816(acc[mf][nf], aH[mf], bH[nf]);
        }
        buf ^= 1;
    }

#pragma unroll
    for (int mf = 0; mf < 4; mf++) {
#pragma unroll
        for (int nf = 0; nf < 8; nf++) {
            int nl = wn * 64 + nf * 8 + (lid & 3) * 2;
            int n = n0 + nl;
            float b0 = biasS[nl], b1 = biasS[nl + 1];
#pragma unroll
            for (int half = 0; half < 2; half++) {
                int m = m0 + wm * 64 + mf * 16 + (lid >> 2) + half * 8;
                *(float2*)(Cout + (size_t)m * Dd + n) =
                    make_float2(acc[mf][nf][half * 2 + 0] + b0,
                                acc[mf][nf][half * 2 + 1] + b1);
            }
        }
    }
}

// ---------------------------------------------------------------------------
// Tensor-core causal flash attention. S = q16@k16 (1 term — q storage error
// contributes ~2.4e-4 to the exponent, averaged by softmax);
// O += P16@v16 (1 term). KV ring 3-stage. q-tile 128 rows, 256 thr / 8 warps.
// ---------------------------------------------------------------------------
#define AT_STRIDE 144
#define QT_B     (128 * AT_STRIDE)           // 18432 (single q tile)
#define KV_TILE  (64 * AT_STRIDE)            // 9216
#define KV0      QT_B                        // 18432
#define KV_STAGE (2 * KV_TILE)               // 18432 (k + v)
#define ATTN_SMEM (KV0 + 3 * KV_STAGE)       // 73728

__global__ __launch_bounds__(256, 2)
void attn_mma()
{
    extern __shared__ char smem[];
    const uint32_t sb = smem_to_u32(smem);
    const int pr = blockIdx.x;                 // pair index 0..7
    const int bh = blockIdx.y;
    const int b = bh >> 4, h = bh & 15;
    const int tid = threadIdx.x, wid = tid >> 5, lid = tid & 31;

    const __half* kbase = g_kh + (size_t)bh * Ss * HD;
    const __half* vbase = g_vh + (size_t)bh * Ss * HD;

    auto issue = [&](int kt, int st) {
#pragma unroll
        for (int i = 0; i < 4; i++) {
            int idx = tid + i * 256;
            int t = idx >> 9, w = idx & 511;
            int r = w >> 3, c = w & 7;
            const __half* src = (t ? vbase : kbase) + (size_t)(kt * 64 + r) * HD + c * 8;
            cp_async16(sb + KV0 + st * KV_STAGE + t * KV_TILE + r * AT_STRIDE + c * 16, src);
        }
        cp_commit();
    };

    const uint32_t qrowb = (wid * 16 + (lid & 15)) * AT_STRIDE + (lid >> 4) * 16;
    const uint32_t krowb = (((lid >> 4) << 3) + (lid & 7)) * AT_STRIDE + ((lid >> 3) & 1) * 16;
    const uint32_t vrowb = (lid & 15) * AT_STRIDE + ((lid >> 4) & 1) * 16;

    for (int half_t = 0; half_t < 2; half_t++) {
        const int qt = half_t ? (15 - pr) : pr;       // q-tile of 128 rows
        const __half* QB = g_q16 + ((size_t)bh * Ss + qt * 128) * HD;
        const int nk = 2 * qt + 2;

        // Q tile: 128 rows x 128B
#pragma unroll
        for (int i = 0; i < 4; i++) {
            int idx = tid + i * 256;
            int r = idx >> 3, c = idx & 7;
            cp_async16(sb + r * AT_STRIDE + c * 16, QB + (size_t)r * HD + c * 8);
        }
        cp_commit();
        issue(0, 0);
        if (nk > 1) issue(1, 1);

        float acc[8][4];
#pragma unroll
        for (int i = 0; i < 8; i++)
#pragma unroll
            for (int j = 0; j < 4; j++) acc[i][j] = 0.f;
        float mrow[2] = { -1e30f, -1e30f }, lrow[2] = { 0.f, 0.f };

        int stage = 0;
        for (int kt = 0; kt < nk; kt++) {
            if (kt + 1 < nk) cp_wait<1>(); else cp_wait<0>();
            __syncthreads();          // chunk kt (and Q) ready + old stage reads done
            if (kt + 2 < nk) issue(kt + 2, (kt + 2) % 3);

            const uint32_t kbt = sb + KV0 + stage * KV_STAGE;
            const uint32_t vbt = kbt + KV_TILE;

            // ---- S = q16 @ k16^T  (1 MMA term) ----
            float sf[8][4];
#pragma unroll
            for (int i = 0; i < 8; i++)
#pragma unroll
                for (int j = 0; j < 4; j++) sf[i][j] = 0.f;

#pragma unroll
            for (int kk = 0; kk < 4; kk++) {
                uint32_t aH[4];
                ldsm_x4(aH, sb + qrowb + kk * 32);
#pragma unroll
                for (int nf2 = 0; nf2 < 4; nf2++) {
                    uint32_t rH[4];
                    ldsm_x4(rH, kbt + nf2 * 16 * AT_STRIDE + krowb + kk * 32);
                    mma16816(sf[nf2 * 2],     aH, rH);
                    mma16816(sf[nf2 * 2 + 1], aH, rH + 2);
                }
            }

            if (kt >= 2 * qt) {     // diagonal region: causal mask
                int r0 = wid * 16 + (lid >> 2);
                int coff = kt * 64 - qt * 128;
#pragma unroll
                for (int nf = 0; nf < 8; nf++) {
                    int c0 = coff + nf * 8 + (lid & 3) * 2;
                    if (c0     > r0)     sf[nf][0] = -1e30f;
                    if (c0 + 1 > r0)     sf[nf][1] = -1e30f;
                    if (c0     > r0 + 8) sf[nf][2] = -1e30f;
                    if (c0 + 1 > r0 + 8) sf[nf][3] = -1e30f;
                }
            }

            // ---- online softmax in exp2 domain ----
#pragma unroll
            for (int hf = 0; hf < 2; hf++) {
                float mx = -1e30f;
#pragma unroll
                for (int nf = 0; nf < 8; nf++)
                    mx = fmaxf(mx, fmaxf(sf[nf][hf * 2], sf[nf][hf * 2 + 1]));
                mx = fmaxf(mx, __shfl_xor_sync(0xffffffffu, mx, 1));
                mx = fmaxf(mx, __shfl_xor_sync(0xffffffffu, mx, 2));
                float mnew = fmaxf(mrow[hf], mx);
                float alpha = ex2(mrow[hf] - mnew);
                mrow[hf] = mnew;
                float sum = 0.f;
#pragma unroll
                for (int nf = 0; nf < 8; nf++) {
                    sf[nf][hf * 2]     = ex2(sf[nf][hf * 2] - mnew);
                    sf[nf][hf * 2 + 1] = ex2(sf[nf][hf * 2 + 1] - mnew);
                    sum += sf[nf][hf * 2] + sf[nf][hf * 2 + 1];
                }
                sum += __shfl_xor_sync(0xffffffffu, sum, 1);
                sum += __shfl_xor_sync(0xffffffffu, sum, 2);
                lrow[hf] = lrow[hf] * alpha + sum;
#pragma unroll
                for (int nf = 0; nf < 8; nf++) {
                    acc[nf][hf * 2]     *= alpha;
                    acc[nf][hf * 2 + 1] *= alpha;
                }
            }

            // ---- O += P16 @ v16  (1 MMA term) ----
#pragma unroll
            for (int kk2 = 0; kk2 < 4; kk2++) {
                uint32_t aPh[4];
#pragma unroll
                for (int q = 0; q < 2; q++) {
                    const float* c = sf[kk2 * 2 + q];
                    aPh[q * 2]     = packh(c[0], c[1]);
                    aPh[q * 2 + 1] = packh(c[2], c[3]);
                }
#pragma unroll
                for (int nf2 = 0; nf2 < 4; nf2++) {
                    uint32_t vH[4];
                    ldsm_x4_t(vH, vbt + (kk2 * 16) * AT_STRIDE + vrowb + nf2 * 32);
                    mma16816(acc[nf2 * 2],     aPh, vH);
                    mma16816(acc[nf2 * 2 + 1], aPh, vH + 2);
                }
            }
            stage = (stage == 2) ? 0 : stage + 1;
        }

        // ---- epilogue: ctx -> single fp16 (B,S,D) ----
        float inv0 = 1.f / lrow[0], inv1 = 1.f / lrow[1];
        int r0 = qt * 128 + wid * 16 + (lid >> 2);
#pragma unroll
        for (int nf = 0; nf < 8; nf++) {
            int d0 = h * HD + nf * 8 + (lid & 3) * 2;
            size_t o0 = ((size_t)b * Ss + r0) * Dd + d0;
            size_t o1 = ((size_t)b * Ss + r0 + 8) * Dd + d0;
            *(__half2*)(g_c16 + o0) =
                __floats2half2_rn(acc[nf][0] * inv0, acc[nf][1] * inv0);
            *(__half2*)(g_c16 + o1) =
                __floats2half2_rn(acc[nf][2] * inv1, acc[nf][3] * inv1);
        }
        __syncthreads();    // all smem reads done before next half's loads
    }
}

// ---------------------------------------------------------------------------
extern "C" void kernel_launch(void* const* d_in, const int* in_sizes, int n_in,
                              void* d_out, int out_size)
{
    const float* x  = (const float*)d_in[0];
    const float* Wq = (const float*)d_in[1];
    const float* bq = (const float*)d_in[2];
    const float* Wk = (const float*)d_in[3];
    const float* bk = (const float*)d_in[4];
    const float* Wv = (const float*)d_in[5];
    const float* bv = (const float*)d_in[6];
    const float* Wo = (const float*)d_in[7];
    const float* bo = (const float*)d_in[8];
    float* out = (float*)d_out;

    cudaFuncSetAttribute(gemm_qkv, cudaFuncAttributeMaxDynamicSharedMemorySize, QKV_SMEM);
    cudaFuncSetAttribute(gemm_out, cudaFuncAttributeMaxDynamicSharedMemorySize, OUT_SMEM);
    cudaFuncSetAttribute(attn_mma, cudaFuncAttributeMaxDynamicSharedMemorySize, ATTN_SMEM);

    split_all<<<(Mtot * Dd + 4 * Dd * Dd) / 4096, 256>>>(x, Wq, Wk, Wv, Wo);

    gemm_qkv<<<dim3(Dd / 128, Mtot / 128, 3), 128, QKV_SMEM>>>(bq, bk, bv);

    attn_mma<<<dim3(8, Bb * Hh), 256, ATTN_SMEM>>>();

    gemm_out<<<dim3(Dd / 128, Mtot / 128), 128, OUT_SMEM>>>(bo, out);
}

// round 16
// speedup vs baseline: 1.1952x; 1.1219x over previous
#include <cuda_runtime.h>
#include <cuda_fp16.h>
#include <cstdint>

#define Bb 2
#define Ss 2048
#define Dd 1024
#define Hh 16
#define HD 64
#define Mtot (Bb*Ss)   // 4096
#define QSCALE 0.1803368801111244f   // 0.125 * log2(e): softmax in exp2 domain

// ---------------- scratch (static device arrays; alloc APIs forbidden) -----
__device__ __align__(16) __half g_q16[Bb*Hh*Ss*HD]; // q single fp16 (B,H,S,hd)
__device__ __align__(16) __half g_kh[Bb*Hh*Ss*HD];  // k single fp16
__device__ __align__(16) __half g_vh[Bb*Hh*Ss*HD];  // v single fp16
__device__ __align__(16) __half g_x16[Mtot*Dd];     // x single fp16
__device__ __align__(16) __half g_w [4u*Dd*Dd];     // Wq,Wk,Wv,Wo single fp16
__device__ __align__(16) __half g_c16[Mtot*Dd];     // ctx single fp16 (B,S,D)

// ---------------- PTX helpers (sm_80/75-era only) --------------------------
__device__ __forceinline__ uint32_t smem_to_u32(const void* p) {
    uint32_t a;
    asm("{ .reg .u64 t; cvta.to.shared.u64 t, %1; cvt.u32.u64 %0, t; }"
        : "=r"(a) : "l"(p));
    return a;
}
__device__ __forceinline__ void cp_async16(uint32_t dst, const void* src) {
    asm volatile("cp.async.cg.shared.global [%0], [%1], 16;"
                 :: "r"(dst), "l"(src) : "memory");
}
__device__ __forceinline__ void cp_commit() {
    asm volatile("cp.async.commit_group;" ::: "memory");
}
template<int N> __device__ __forceinline__ void cp_wait() {
    asm volatile("cp.async.wait_group %0;" :: "n"(N) : "memory");
}
__device__ __forceinline__ void ldsm_x4(uint32_t* r, uint32_t addr) {
    asm volatile("ldmatrix.sync.aligned.m8n8.x4.shared.b16 {%0,%1,%2,%3}, [%4];"
                 : "=r"(r[0]), "=r"(r[1]), "=r"(r[2]), "=r"(r[3]) : "r"(addr));
}
__device__ __forceinline__ void ldsm_x4_t(uint32_t* r, uint32_t addr) {
    asm volatile("ldmatrix.sync.aligned.m8n8.x4.trans.shared.b16 {%0,%1,%2,%3}, [%4];"
                 : "=r"(r[0]), "=r"(r[1]), "=r"(r[2]), "=r"(r[3]) : "r"(addr));
}
__device__ __forceinline__ void mma16816(float* c, const uint32_t* a, const uint32_t* b) {
    asm volatile("mma.sync.aligned.m16n8k16.row.col.f32.f16.f16.f32 "
                 "{%0,%1,%2,%3}, {%4,%5,%6,%7}, {%8,%9}, {%0,%1,%2,%3};"
                 : "+f"(c[0]), "+f"(c[1]), "+f"(c[2]), "+f"(c[3])
                 : "r"(a[0]), "r"(a[1]), "r"(a[2]), "r"(a[3]), "r"(b[0]), "r"(b[1]));
}
__device__ __forceinline__ float ex2(float x) {
    float y;
    asm("ex2.approx.ftz.f32 %0, %1;" : "=f"(y) : "f"(x));
    return y;
}
__device__ __forceinline__ uint32_t packh(float a, float b) {
    __half2 t = __floats2half2_rn(a, b);
    return *(uint32_t*)&t;
}

// Round x + all 4 weights to fp16 (8M fp32 total). MLP=4.
__global__ __launch_bounds__(256)
void split_all(const float* __restrict__ x,  const float* __restrict__ Wq,
               const float* __restrict__ Wk, const float* __restrict__ Wv,
               const float* __restrict__ Wo)
{
#pragma unroll
    for (int p = 0; p < 4; p++) {
        int i = blockIdx.x * 4096 + p * 1024 + threadIdx.x * 4;
        const float* src;
        __half* dst;
        if (i < Mtot * Dd) {
            src = x + i; dst = g_x16 + i;
        } else {
            int j = i - Mtot * Dd;
            int w = j >> 20;                 // Dd*Dd = 2^20
            int r = j & (Dd * Dd - 1);
            src = (w == 0 ? Wq : w == 1 ? Wk : w == 2 ? Wv : Wo) + r;
            dst = g_w + j;
        }
        float4 v = *(const float4*)src;
        *(__half2*)(dst)     = __floats2half2_rn(v.x, v.y);
        *(__half2*)(dst + 2) = __floats2half2_rn(v.z, v.w);
    }
}

// ---------------------------------------------------------------------------
// mma.sync GEMM cores. Block 128x128, FOUR warps (2x2 grid of 64x64 warp
// tiles), 2-stage cp.async double buffer, uniform 1-term.
// qkv: {q,k,v} = x16 @ W^T (+bias); q pre-scaled by QSCALE. fp16 outputs with
// head permute. out: out = c16 @ Wo^T + bo, fp32.
// ---------------------------------------------------------------------------
#define TILE_B   10240                 // 128 rows * 80 B
#define BUF2_B   (2 * TILE_B)          // stage: A, W
#define GEMM_SMEM (2 * BUF2_B + 512)   // 41472

// Fused QKV projection: gridDim.z selects Q/K/V (all 1-term).
__global__ __launch_bounds__(128)
void gemm_qkv(const float* __restrict__ bq, const float* __restrict__ bk,
              const float* __restrict__ bv)
{
    extern __shared__ char smem[];
    const uint32_t sb = smem_to_u32(smem);
    float* biasS = (float*)(smem + 2 * BUF2_B);

    const int tid = threadIdx.x, wid = tid >> 5, lid = tid & 31;
    const int wm = wid >> 1, wn = wid & 1;
    const int m0 = blockIdx.y * 128, n0 = blockIdx.x * 128;
    const int z = blockIdx.z;

    const float* bias = (z == 0) ? bq : (z == 1) ? bk : bv;
    const __half* W16 = g_w + (size_t)z * Dd * Dd;

    biasS[tid] = bias[n0 + tid];

    float acc[4][8][4];
#pragma unroll
    for (int i = 0; i < 4; i++)
#pragma unroll
        for (int j = 0; j < 8; j++)
#pragma unroll
            for (int k = 0; k < 4; k++) acc[i][j][k] = 0.f;

    auto issue = [&](int kt, int st) {
        const int kc = kt * 32;
#pragma unroll
        for (int i = 0; i < 8; i++) {
            int idx = tid + i * 128;
            int tile = idx >> 9, w = idx & 511;
            int r = w >> 2, seg = (w & 3) * 16;
            uint32_t dst = sb + st * BUF2_B + tile * TILE_B + r * 80 + seg;
            const char* src;
            if (tile == 0) src = (const char*)(g_x16 + (size_t)(m0 + r) * Dd + kc) + seg;
            else           src = (const char*)(W16 + (size_t)(n0 + r) * Dd + kc) + seg;
            cp_async16(dst, src);
        }
        cp_commit();
    };

    issue(0, 0);
    const int arow0 = wm * 64 + (lid & 15);
    const int abyte0 = (lid >> 4) * 16;
    const int brow0 = wn * 64 + ((lid >> 4) << 3) + (lid & 7);
    const int bbyte0 = ((lid >> 3) & 1) * 16;

    int buf = 0;
    for (int kt = 0; kt < 32; kt++) {
        cp_wait<0>();
        __syncthreads();               // data ready + prior reads of buf^1 done
        if (kt + 1 < 32) issue(kt + 1, buf ^ 1);

        const uint32_t tA = sb + buf * BUF2_B;
        const uint32_t tB = tA + TILE_B;

#pragma unroll
        for (int kk = 0; kk < 2; kk++) {
            const int ab = kk * 32 + abyte0;
            const int bb = kk * 32 + bbyte0;
            uint32_t aH[4][4], bH[8][2];
#pragma unroll
            for (int mf = 0; mf < 4; mf++)
                ldsm_x4(aH[mf], tA + (arow0 + mf * 16) * 80 + ab);
#pragma unroll
            for (int nf2 = 0; nf2 < 4; nf2++) {
                uint32_t r4[4];
                ldsm_x4(r4, tB + (brow0 + nf2 * 16) * 80 + bb);
                bH[nf2 * 2][0] = r4[0]; bH[nf2 * 2][1] = r4[1];
                bH[nf2 * 2 + 1][0] = r4[2]; bH[nf2 * 2 + 1][1] = r4[3];
            }
#pragma unroll
            for (int mf = 0; mf < 4; mf++)
#pragma unroll
                for (int nf = 0; nf < 8; nf++)
                    mma16816(acc[mf][nf], aH[mf], bH[nf]);
        }
        buf ^= 1;
    }

    const float scale = (z == 0) ? QSCALE : 1.f;
    __half* dst = (z == 0) ? g_q16 : (z == 1) ? g_kh : g_vh;
#pragma unroll
    for (int mf = 0; mf < 4; mf++) {
#pragma unroll
        for (int nf = 0; nf < 8; nf++) {
            int nl = wn * 64 + nf * 8 + (lid & 3) * 2;
            int n = n0 + nl;
            float b0 = biasS[nl], b1 = biasS[nl + 1];
#pragma unroll
            for (int half = 0; half < 2; half++) {
                int m = m0 + wm * 64 + mf * 16 + (lid >> 2) + half * 8;
                float v0 = (acc[mf][nf][half * 2 + 0] + b0) * scale;
                float v1 = (acc[mf][nf][half * 2 + 1] + b1) * scale;
                int b = m >> 11, s = m & (Ss - 1);
                int hh = n >> 6, d = n & (HD - 1);
                size_t o = (((size_t)(b * Hh + hh)) * Ss + s) * HD + d;
                *(__half2*)(dst + o) = __floats2half2_rn(v0, v1);
            }
        }
    }
}

// Output GEMM: out = c16 @ Wo16^T + bo, fp32 result (1 term).
__global__ __launch_bounds__(128)
void gemm_out(const float* __restrict__ bias, float* __restrict__ Cout)
{
    extern __shared__ char smem[];
    const uint32_t sb = smem_to_u32(smem);
    float* biasS = (float*)(smem + 2 * BUF2_B);

    const int tid = threadIdx.x, wid = tid >> 5, lid = tid & 31;
    const int wm = wid >> 1, wn = wid & 1;
    const int m0 = blockIdx.y * 128, n0 = blockIdx.x * 128;

    const __half* W16 = g_w + (size_t)3 * Dd * Dd;

    biasS[tid] = bias[n0 + tid];

    float acc[4][8][4];
#pragma unroll
    for (int i = 0; i < 4; i++)
#pragma unroll
        for (int j = 0; j < 8; j++)
#pragma unroll
            for (int k = 0; k < 4; k++) acc[i][j][k] = 0.f;

    auto issue = [&](int kt, int st) {
        const int kc = kt * 32;
#pragma unroll
        for (int i = 0; i < 8; i++) {
            int idx = tid + i * 128;
            int tile = idx >> 9, w = idx & 511;
            int r = w >> 2, seg = (w & 3) * 16;
            uint32_t dst = sb + st * BUF2_B + tile * TILE_B + r * 80 + seg;
            const char* src;
            if (tile == 0) src = (const char*)(g_c16 + (size_t)(m0 + r) * Dd + kc) + seg;
            else           src = (const char*)(W16 + (size_t)(n0 + r) * Dd + kc) + seg;
            cp_async16(dst, src);
        }
        cp_commit();
    };

    issue(0, 0);
    const int arow0 = wm * 64 + (lid & 15);
    const int abyte0 = (lid >> 4) * 16;
    const int brow0 = wn * 64 + ((lid >> 4) << 3) + (lid & 7);
    const int bbyte0 = ((lid >> 3) & 1) * 16;

    int buf = 0;
    for (int kt = 0; kt < 32; kt++) {
        cp_wait<0>();
        __syncthreads();
        if (kt + 1 < 32) issue(kt + 1, buf ^ 1);

        const uint32_t tA = sb + buf * BUF2_B;
        const uint32_t tB = tA + TILE_B;

#pragma unroll
        for (int kk = 0; kk < 2; kk++) {
            const int ab = kk * 32 + abyte0;
            const int bb = kk * 32 + bbyte0;
            uint32_t aH[4][4], bH[8][2];
#pragma unroll
            for (int mf = 0; mf < 4; mf++)
                ldsm_x4(aH[mf], tA + (arow0 + mf * 16) * 80 + ab);
#pragma unroll
            for (int nf2 = 0; nf2 < 4; nf2++) {
                uint32_t r4[4];
                ldsm_x4(r4, tB + (brow0 + nf2 * 16) * 80 + bb);
                bH[nf2 * 2][0] = r4[0]; bH[nf2 * 2][1] = r4[1];
                bH[nf2 * 2 + 1][0] = r4[2]; bH[nf2 * 2 + 1][1] = r4[3];
            }
#pragma unroll
            for (int mf = 0; mf < 4; mf++)
#pragma unroll
                for (int nf = 0; nf < 8; nf++)
                    mma16816(acc[mf][nf], aH[mf], bH[nf]);
        }
        buf ^= 1;
    }

#pragma unroll
    for (int mf = 0; mf < 4; mf++) {
#pragma unroll
        for (int nf = 0; nf < 8; nf++) {
            int nl = wn * 64 + nf * 8 + (lid & 3) * 2;
            int n = n0 + nl;
            float b0 = biasS[nl], b1 = biasS[nl + 1];
#pragma unroll
            for (int half = 0; half < 2; half++) {
                int m = m0 + wm * 64 + mf * 16 + (lid >> 2) + half * 8;
                *(float2*)(Cout + (size_t)m * Dd + n) =
                    make_float2(acc[mf][nf][half * 2 + 0] + b0,
                                acc[mf][nf][half * 2 + 1] + b1);
            }
        }
    }
}

// ---------------------------------------------------------------------------
// Tensor-core causal flash attention. S = q16@k16 (1 term);
// O += P16@v16 (1 term). KV ring 3-stage. q-tile 128 rows, 256 thr / 8 warps.
// Paired q-tiles (pr, 15-pr) -> uniform work per CTA.
// ---------------------------------------------------------------------------
#define AT_STRIDE 144
#define QT_B     (128 * AT_STRIDE)           // 18432 (single q tile)
#define KV_TILE  (64 * AT_STRIDE)            // 9216
#define KV0      QT_B                        // 18432
#define KV_STAGE (2 * KV_TILE)               // 18432 (k + v)
#define ATTN_SMEM (KV0 + 3 * KV_STAGE)       // 73728

__global__ __launch_bounds__(256, 2)
void attn_mma()
{
    extern __shared__ char smem[];
    const uint32_t sb = smem_to_u32(smem);
    const int pr = blockIdx.x;                 // pair index 0..7
    const int bh = blockIdx.y;
    const int b = bh >> 4, h = bh & 15;
    const int tid = threadIdx.x, wid = tid >> 5, lid = tid & 31;

    const __half* kbase = g_kh + (size_t)bh * Ss * HD;
    const __half* vbase = g_vh + (size_t)bh * Ss * HD;

    auto issue = [&](int kt, int st) {
#pragma unroll
        for (int i = 0; i < 4; i++) {
            int idx = tid + i * 256;
            int t = idx >> 9, w = idx & 511;
            int r = w >> 3, c = w & 7;
            const __half* src = (t ? vbase : kbase) + (size_t)(kt * 64 + r) * HD + c * 8;
            cp_async16(sb + KV0 + st * KV_STAGE + t * KV_TILE + r * AT_STRIDE + c * 16, src);
        }
        cp_commit();
    };

    const uint32_t qrowb = (wid * 16 + (lid & 15)) * AT_STRIDE + (lid >> 4) * 16;
    const uint32_t krowb = (((lid >> 4) << 3) + (lid & 7)) * AT_STRIDE + ((lid >> 3) & 1) * 16;
    const uint32_t vrowb = (lid & 15) * AT_STRIDE + ((lid >> 4) & 1) * 16;

    for (int half_t = 0; half_t < 2; half_t++) {
        const int qt = half_t ? (15 - pr) : pr;       // q-tile of 128 rows
        const __half* QB = g_q16 + ((size_t)bh * Ss + qt * 128) * HD;
        const int nk = 2 * qt + 2;

        // Q tile: 128 rows x 128B
#pragma unroll
        for (int i = 0; i < 4; i++) {
            int idx = tid + i * 256;
            int r = idx >> 3, c = idx & 7;
            cp_async16(sb + r * AT_STRIDE + c * 16, QB + (size_t)r * HD + c * 8);
        }
        cp_commit();
        issue(0, 0);
        if (nk > 1) issue(1, 1);

        float acc[8][4];
#pragma unroll
        for (int i = 0; i < 8; i++)
#pragma unroll
            for (int j = 0; j < 4; j++) acc[i][j] = 0.f;
        float mrow[2] = { -1e30f, -1e30f }, lrow[2] = { 0.f, 0.f };

        int stage = 0;
        for (int kt = 0; kt < nk; kt++) {
            if (kt + 1 < nk) cp_wait<1>(); else cp_wait<0>();
            __syncthreads();          // chunk kt (and Q) ready + old stage reads done
            if (kt + 2 < nk) issue(kt + 2, (kt + 2) % 3);

            const uint32_t kbt = sb + KV0 + stage * KV_STAGE;
            const uint32_t vbt = kbt + KV_TILE;

            // ---- S = q16 @ k16^T  (1 MMA term) ----
            float sf[8][4];
#pragma unroll
            for (int i = 0; i < 8; i++)
#pragma unroll
                for (int j = 0; j < 4; j++) sf[i][j] = 0.f;

#pragma unroll
            for (int kk = 0; kk < 4; kk++) {
                uint32_t aH[4];
                ldsm_x4(aH, sb + qrowb + kk * 32);
#pragma unroll
                for (int nf2 = 0; nf2 < 4; nf2++) {
                    uint32_t rH[4];
                    ldsm_x4(rH, kbt + nf2 * 16 * AT_STRIDE + krowb + kk * 32);
                    mma16816(sf[nf2 * 2],     aH, rH);
                    mma16816(sf[nf2 * 2 + 1], aH, rH + 2);
                }
            }

            if (kt >= 2 * qt) {     // diagonal region: causal mask
                int r0 = wid * 16 + (lid >> 2);
                int coff = kt * 64 - qt * 128;
#pragma unroll
                for (int nf = 0; nf < 8; nf++) {
                    int c0 = coff + nf * 8 + (lid & 3) * 2;
                    if (c0     > r0)     sf[nf][0] = -1e30f;
                    if (c0 + 1 > r0)     sf[nf][1] = -1e30f;
                    if (c0     > r0 + 8) sf[nf][2] = -1e30f;
                    if (c0 + 1 > r0 + 8) sf[nf][3] = -1e30f;
                }
            }

            // ---- online softmax in exp2 domain ----
#pragma unroll
            for (int hf = 0; hf < 2; hf++) {
                float mx = -1e30f;
#pragma unroll
                for (int nf = 0; nf < 8; nf++)
                    mx = fmaxf(mx, fmaxf(sf[nf][hf * 2], sf[nf][hf * 2 + 1]));
                mx = fmaxf(mx, __shfl_xor_sync(0xffffffffu, mx, 1));
                mx = fmaxf(mx, __shfl_xor_sync(0xffffffffu, mx, 2));
                float mnew = fmaxf(mrow[hf], mx);
                float alpha = ex2(mrow[hf] - mnew);
                mrow[hf] = mnew;
                float sum = 0.f;
#pragma unroll
                for (int nf = 0; nf < 8; nf++) {
                    sf[nf][hf * 2]     = ex2(sf[nf][hf * 2] - mnew);
                    sf[nf][hf * 2 + 1] = ex2(sf[nf][hf * 2 + 1] - mnew);
                    sum += sf[nf][hf * 2] + sf[nf][hf * 2 + 1];
                }
                sum += __shfl_xor_sync(0xffffffffu, sum, 1);
                sum += __shfl_xor_sync(0xffffffffu, sum, 2);
                lrow[hf] = lrow[hf] * alpha + sum;
#pragma unroll
                for (int nf = 0; nf < 8; nf++) {
                    acc[nf][hf * 2]     *= alpha;
                    acc[nf][hf * 2 + 1] *= alpha;
                }
            }

            // ---- O += P16 @ v16  (1 MMA term) ----
#pragma unroll
            for (int kk2 = 0; kk2 < 4; kk2++) {
                uint32_t aPh[4];
#pragma unroll
                for (int q = 0; q < 2; q++) {
                    const float* c = sf[kk2 * 2 + q];
                    aPh[q * 2]     = packh(c[0], c[1]);
                    aPh[q * 2 + 1] = packh(c[2], c[3]);
                }
#pragma unroll
                for (int nf2 = 0; nf2 < 4; nf2++) {
                    uint32_t vH[4];
                    ldsm_x4_t(vH, vbt + (kk2 * 16) * AT_STRIDE + vrowb + nf2 * 32);
                    mma16816(acc[nf2 * 2],     aPh, vH);
                    mma16816(acc[nf2 * 2 + 1], aPh, vH + 2);
                }
            }
            stage = (stage == 2) ? 0 : stage + 1;
        }

        // ---- epilogue: ctx -> single fp16 (B,S,D) ----
        float inv0 = 1.f / lrow[0], inv1 = 1.f / lrow[1];
        int r0 = qt * 128 + wid * 16 + (lid >> 2);
#pragma unroll
        for (int nf = 0; nf < 8; nf++) {
            int d0 = h * HD + nf * 8 + (lid & 3) * 2;
            size_t o0 = ((size_t)b * Ss + r0) * Dd + d0;
            size_t o1 = ((size_t)b * Ss + r0 + 8) * Dd + d0;
            *(__half2*)(g_c16 + o0) =
                __floats2half2_rn(acc[nf][0] * inv0, acc[nf][1] * inv0);
            *(__half2*)(g_c16 + o1) =
                __floats2half2_rn(acc[nf][2] * inv1, acc[nf][3] * inv1);
        }
        __syncthreads();    // all smem reads done before next half's loads
    }
}

// ---------------------------------------------------------------------------
extern "C" void kernel_launch(void* const* d_in, const int* in_sizes, int n_in,
                              void* d_out, int out_size)
{
    const float* x  = (const float*)d_in[0];
    const float* Wq = (const float*)d_in[1];
    const float* bq = (const float*)d_in[2];
    const float* Wk = (const float*)d_in[3];
    const float* bk = (const float*)d_in[4];
    const float* Wv = (const float*)d_in[5];
    const float* bv = (const float*)d_in[6];
    const float* Wo = (const float*)d_in[7];
    const float* bo = (const float*)d_in[8];
    float* out = (float*)d_out;

    cudaFuncSetAttribute(gemm_qkv, cudaFuncAttributeMaxDynamicSharedMemorySize, GEMM_SMEM);
    cudaFuncSetAttribute(gemm_out, cudaFuncAttributeMaxDynamicSharedMemorySize, GEMM_SMEM);
    cudaFuncSetAttribute(attn_mma, cudaFuncAttributeMaxDynamicSharedMemorySize, ATTN_SMEM);

    split_all<<<(Mtot * Dd + 4 * Dd * Dd) / 4096, 256>>>(x, Wq, Wk, Wv, Wo);

    gemm_qkv<<<dim3(Dd / 128, Mtot / 128, 3), 128, GEMM_SMEM>>>(bq, bk, bv);

    attn_mma<<<dim3(8, Bb * Hh), 256, ATTN_SMEM>>>();

    gemm_out<<<dim3(Dd / 128, Mtot / 128), 128, GEMM_SMEM>>>(bo, out);
}

// round 17
// speedup vs baseline: 1.2542x; 1.0494x over previous
#include <cuda_runtime.h>
#include <cuda_fp16.h>
#include <cstdint>

#define Bb 2
#define Ss 2048
#define Dd 1024
#define Hh 16
#define HD 64
#define Mtot (Bb*Ss)   // 4096
#define QSCALE 0.1803368801111244f   // 0.125 * log2(e): softmax in exp2 domain

// ---------------- scratch (static device arrays; alloc APIs forbidden) -----
__device__ __align__(16) __half g_q16[Bb*Hh*Ss*HD]; // q single fp16 (B,H,S,hd)
__device__ __align__(16) __half g_kh[Bb*Hh*Ss*HD];  // k single fp16
__device__ __align__(16) __half g_vh[Bb*Hh*Ss*HD];  // v single fp16
__device__ __align__(16) __half g_x16[Mtot*Dd];     // x single fp16
__device__ __align__(16) __half g_w [4u*Dd*Dd];     // Wq,Wk,Wv,Wo single fp16
__device__ __align__(16) __half g_c16[Mtot*Dd];     // ctx single fp16 (B,S,D)

// ---------------- PTX helpers (sm_80/75-era only) --------------------------
__device__ __forceinline__ uint32_t smem_to_u32(const void* p) {
    uint32_t a;
    asm("{ .reg .u64 t; cvta.to.shared.u64 t, %1; cvt.u32.u64 %0, t; }"
        : "=r"(a) : "l"(p));
    return a;
}
__device__ __forceinline__ void cp_async16(uint32_t dst, const void* src) {
    asm volatile("cp.async.cg.shared.global [%0], [%1], 16;"
                 :: "r"(dst), "l"(src) : "memory");
}
__device__ __forceinline__ void cp_commit() {
    asm volatile("cp.async.commit_group;" ::: "memory");
}
template<int N> __device__ __forceinline__ void cp_wait() {
    asm volatile("cp.async.wait_group %0;" :: "n"(N) : "memory");
}
__device__ __forceinline__ void ldsm_x4(uint32_t* r, uint32_t addr) {
    asm volatile("ldmatrix.sync.aligned.m8n8.x4.shared.b16 {%0,%1,%2,%3}, [%4];"
                 : "=r"(r[0]), "=r"(r[1]), "=r"(r[2]), "=r"(r[3]) : "r"(addr));
}
__device__ __forceinline__ void ldsm_x4_t(uint32_t* r, uint32_t addr) {
    asm volatile("ldmatrix.sync.aligned.m8n8.x4.trans.shared.b16 {%0,%1,%2,%3}, [%4];"
                 : "=r"(r[0]), "=r"(r[1]), "=r"(r[2]), "=r"(r[3]) : "r"(addr));
}
__device__ __forceinline__ void mma16816(float* c, const uint32_t* a, const uint32_t* b) {
    asm volatile("mma.sync.aligned.m16n8k16.row.col.f32.f16.f16.f32 "
                 "{%0,%1,%2,%3}, {%4,%5,%6,%7}, {%8,%9}, {%0,%1,%2,%3};"
                 : "+f"(c[0]), "+f"(c[1]), "+f"(c[2]), "+f"(c[3])
                 : "r"(a[0]), "r"(a[1]), "r"(a[2]), "r"(a[3]), "r"(b[0]), "r"(b[1]));
}
__device__ __forceinline__ float ex2(float x) {
    float y;
    asm("ex2.approx.ftz.f32 %0, %1;" : "=f"(y) : "f"(x));
    return y;
}
__device__ __forceinline__ uint32_t packh(float a, float b) {
    __half2 t = __floats2half2_rn(a, b);
    return *(uint32_t*)&t;
}

// Round x + all 4 weights to fp16 (8M fp32 total). MLP=4.
__global__ __launch_bounds__(256)
void split_all(const float* __restrict__ x,  const float* __restrict__ Wq,
               const float* __restrict__ Wk, const float* __restrict__ Wv,
               const float* __restrict__ Wo)
{
#pragma unroll
    for (int p = 0; p < 4; p++) {
        int i = blockIdx.x * 4096 + p * 1024 + threadIdx.x * 4;
        const float* src;
        __half* dst;
        if (i < Mtot * Dd) {
            src = x + i; dst = g_x16 + i;
        } else {
            int j = i - Mtot * Dd;
            int w = j >> 20;                 // Dd*Dd = 2^20
            int r = j & (Dd * Dd - 1);
            src = (w == 0 ? Wq : w == 1 ? Wk : w == 2 ? Wv : Wo) + r;
            dst = g_w + j;
        }
        float4 v = *(const float4*)src;
        *(__half2*)(dst)     = __floats2half2_rn(v.x, v.y);
        *(__half2*)(dst + 2) = __floats2half2_rn(v.z, v.w);
    }
}

// ---------------------------------------------------------------------------
// mma.sync GEMM cores. Block 128x128, 4 warps (2x2 of 64x64 warp tiles),
// K-CHUNK 64 (16 kt iterations), 2-stage cp.async. Row stride 144B
// (9 slots; consecutive rows step 1 bank -> conflict-free ldmatrix).
// All paths 1-term fp16.
// ---------------------------------------------------------------------------
#define TILE144_B (128 * 144)            // 18432
#define GSTAGE_B  (2 * TILE144_B)        // 36864 (A + B tile)
#define GEMM_SMEM (2 * GSTAGE_B + 512)   // 74240

// Fused QKV projection: gridDim.z selects Q/K/V (all 1-term).
__global__ __launch_bounds__(128)
void gemm_qkv(const float* __restrict__ bq, const float* __restrict__ bk,
              const float* __restrict__ bv)
{
    extern __shared__ char smem[];
    const uint32_t sb = smem_to_u32(smem);
    float* biasS = (float*)(smem + 2 * GSTAGE_B);

    const int tid = threadIdx.x, wid = tid >> 5, lid = tid & 31;
    const int wm = wid >> 1, wn = wid & 1;
    const int m0 = blockIdx.y * 128, n0 = blockIdx.x * 128;
    const int z = blockIdx.z;

    const float* bias = (z == 0) ? bq : (z == 1) ? bk : bv;
    const __half* W16 = g_w + (size_t)z * Dd * Dd;

    biasS[tid] = bias[n0 + tid];

    float acc[4][8][4];
#pragma unroll
    for (int i = 0; i < 4; i++)
#pragma unroll
        for (int j = 0; j < 8; j++)
#pragma unroll
            for (int k = 0; k < 4; k++) acc[i][j][k] = 0.f;

    auto issue = [&](int kt, int st) {
        const int kc = kt * 64;
#pragma unroll
        for (int i = 0; i < 16; i++) {
            int idx = tid + i * 128;
            int tile = idx >> 10, w = idx & 1023;
            int r = w >> 3, seg = (w & 7) * 16;
            uint32_t dst = sb + st * GSTAGE_B + tile * TILE144_B + r * 144 + seg;
            const char* src = (tile == 0)
                ? (const char*)(g_x16 + (size_t)(m0 + r) * Dd + kc) + seg
                : (const char*)(W16 + (size_t)(n0 + r) * Dd + kc) + seg;
            cp_async16(dst, src);
        }
        cp_commit();
    };

    issue(0, 0);
    const int arow0 = wm * 64 + (lid & 15);
    const int abyte0 = (lid >> 4) * 16;
    const int brow0 = wn * 64 + ((lid >> 4) << 3) + (lid & 7);
    const int bbyte0 = ((lid >> 3) & 1) * 16;

    int buf = 0;
    for (int kt = 0; kt < 16; kt++) {
        cp_wait<0>();
        __syncthreads();               // data ready + prior reads of buf^1 done
        if (kt + 1 < 16) issue(kt + 1, buf ^ 1);

        const uint32_t tA = sb + buf * GSTAGE_B;
        const uint32_t tB = tA + TILE144_B;

#pragma unroll
        for (int kk = 0; kk < 4; kk++) {
            const int ab = kk * 32 + abyte0;
            const int bb = kk * 32 + bbyte0;
            uint32_t aH[4][4], bH[8][2];
#pragma unroll
            for (int mf = 0; mf < 4; mf++)
                ldsm_x4(aH[mf], tA + (arow0 + mf * 16) * 144 + ab);
#pragma unroll
            for (int nf2 = 0; nf2 < 4; nf2++) {
                uint32_t r4[4];
                ldsm_x4(r4, tB + (brow0 + nf2 * 16) * 144 + bb);
                bH[nf2 * 2][0] = r4[0]; bH[nf2 * 2][1] = r4[1];
                bH[nf2 * 2 + 1][0] = r4[2]; bH[nf2 * 2 + 1][1] = r4[3];
            }
#pragma unroll
            for (int mf = 0; mf < 4; mf++)
#pragma unroll
                for (int nf = 0; nf < 8; nf++)
                    mma16816(acc[mf][nf], aH[mf], bH[nf]);
        }
        buf ^= 1;
    }

    const float scale = (z == 0) ? QSCALE : 1.f;
    __half* dst = (z == 0) ? g_q16 : (z == 1) ? g_kh : g_vh;
#pragma unroll
    for (int mf = 0; mf < 4; mf++) {
#pragma unroll
        for (int nf = 0; nf < 8; nf++) {
            int nl = wn * 64 + nf * 8 + (lid & 3) * 2;
            int n = n0 + nl;
            float b0 = biasS[nl], b1 = biasS[nl + 1];
#pragma unroll
            for (int half = 0; half < 2; half++) {
                int m = m0 + wm * 64 + mf * 16 + (lid >> 2) + half * 8;
                float v0 = (acc[mf][nf][half * 2 + 0] + b0) * scale;
                float v1 = (acc[mf][nf][half * 2 + 1] + b1) * scale;
                int b = m >> 11, s = m & (Ss - 1);
                int hh = n >> 6, d = n & (HD - 1);
                size_t o = (((size_t)(b * Hh + hh)) * Ss + s) * HD + d;
                *(__half2*)(dst + o) = __floats2half2_rn(v0, v1);
            }
        }
    }
}

// Output GEMM: out = c16 @ Wo16^T + bo, fp32 result (1 term, K-chunk 64).
__global__ __launch_bounds__(128)
void gemm_out(const float* __restrict__ bias, float* __restrict__ Cout)
{
    extern __shared__ char smem[];
    const uint32_t sb = smem_to_u32(smem);
    float* biasS = (float*)(smem + 2 * GSTAGE_B);

    const int tid = threadIdx.x, wid = tid >> 5, lid = tid & 31;
    const int wm = wid >> 1, wn = wid & 1;
    const int m0 = blockIdx.y * 128, n0 = blockIdx.x * 128;

    const __half* W16 = g_w + (size_t)3 * Dd * Dd;

    biasS[tid] = bias[n0 + tid];

    float acc[4][8][4];
#pragma unroll
    for (int i = 0; i < 4; i++)
#pragma unroll
        for (int j = 0; j < 8; j++)
#pragma unroll
            for (int k = 0; k < 4; k++) acc[i][j][k] = 0.f;

    auto issue = [&](int kt, int st) {
        const int kc = kt * 64;
#pragma unroll
        for (int i = 0; i < 16; i++) {
            int idx = tid + i * 128;
            int tile = idx >> 10, w = idx & 1023;
            int r = w >> 3, seg = (w & 7) * 16;
            uint32_t dst = sb + st * GSTAGE_B + tile * TILE144_B + r * 144 + seg;
            const char* src = (tile == 0)
                ? (const char*)(g_c16 + (size_t)(m0 + r) * Dd + kc) + seg
                : (const char*)(W16 + (size_t)(n0 + r) * Dd + kc) + seg;
            cp_async16(dst, src);
        }
        cp_commit();
    };

    issue(0, 0);
    const int arow0 = wm * 64 + (lid & 15);
    const int abyte0 = (lid >> 4) * 16;
    const int brow0 = wn * 64 + ((lid >> 4) << 3) + (lid & 7);
    const int bbyte0 = ((lid >> 3) & 1) * 16;

    int buf = 0;
    for (int kt = 0; kt < 16; kt++) {
        cp_wait<0>();
        __syncthreads();
        if (kt + 1 < 16) issue(kt + 1, buf ^ 1);

        const uint32_t tA = sb + buf * GSTAGE_B;
        const uint32_t tB = tA + TILE144_B;

#pragma unroll
        for (int kk = 0; kk < 4; kk++) {
            const int ab = kk * 32 + abyte0;
            const int bb = kk * 32 + bbyte0;
            uint32_t aH[4][4], bH[8][2];
#pragma unroll
            for (int mf = 0; mf < 4; mf++)
                ldsm_x4(aH[mf], tA + (arow0 + mf * 16) * 144 + ab);
#pragma unroll
            for (int nf2 = 0; nf2 < 4; nf2++) {
                uint32_t r4[4];
                ldsm_x4(r4, tB + (brow0 + nf2 * 16) * 144 + bb);
                bH[nf2 * 2][0] = r4[0]; bH[nf2 * 2][1] = r4[1];
                bH[nf2 * 2 + 1][0] = r4[2]; bH[nf2 * 2 + 1][1] = r4[3];
            }
#pragma unroll
            for (int mf = 0; mf < 4; mf++)
#pragma unroll
                for (int nf = 0; nf < 8; nf++)
                    mma16816(acc[mf][nf], aH[mf], bH[nf]);
        }
        buf ^= 1;
    }

#pragma unroll
    for (int mf = 0; mf < 4; mf++) {
#pragma unroll
        for (int nf = 0; nf < 8; nf++) {
            int nl = wn * 64 + nf * 8 + (lid & 3) * 2;
            int n = n0 + nl;
            float b0 = biasS[nl], b1 = biasS[nl + 1];
#pragma unroll
            for (int half = 0; half < 2; half++) {
                int m = m0 + wm * 64 + mf * 16 + (lid >> 2) + half * 8;
                *(float2*)(Cout + (size_t)m * Dd + n) =
                    make_float2(acc[mf][nf][half * 2 + 0] + b0,
                                acc[mf][nf][half * 2 + 1] + b1);
            }
        }
    }
}

// ---------------------------------------------------------------------------
// Tensor-core causal flash attention. S = q16@k16 (1 term);
// O += P16@v16 (1 term). KV ring 3-stage. q-tile 128 rows, 256 thr / 8 warps.
// Paired q-tiles (pr, 15-pr) -> uniform work per CTA.
// ---------------------------------------------------------------------------
#define AT_STRIDE 144
#define QT_B     (128 * AT_STRIDE)           // 18432 (single q tile)
#define KV_TILE  (64 * AT_STRIDE)            // 9216
#define KV0      QT_B                        // 18432
#define KV_STAGE (2 * KV_TILE)               // 18432 (k + v)
#define ATTN_SMEM (KV0 + 3 * KV_STAGE)       // 73728

__global__ __launch_bounds__(256, 2)
void attn_mma()
{
    extern __shared__ char smem[];
    const uint32_t sb = smem_to_u32(smem);
    const int pr = blockIdx.x;                 // pair index 0..7
    const int bh = blockIdx.y;
    const int b = bh >> 4, h = bh & 15;
    const int tid = threadIdx.x, wid = tid >> 5, lid = tid & 31;

    const __half* kbase = g_kh + (size_t)bh * Ss * HD;
    const __half* vbase = g_vh + (size_t)bh * Ss * HD;

    auto issue = [&](int kt, int st) {
#pragma unroll
        for (int i = 0; i < 4; i++) {
            int idx = tid + i * 256;
            int t = idx >> 9, w = idx & 511;
            int r = w >> 3, c = w & 7;
            const __half* src = (t ? vbase : kbase) + (size_t)(kt * 64 + r) * HD + c * 8;
            cp_async16(sb + KV0 + st * KV_STAGE + t * KV_TILE + r * AT_STRIDE + c * 16, src);
        }
        cp_commit();
    };

    const uint32_t qrowb = (wid * 16 + (lid & 15)) * AT_STRIDE + (lid >> 4) * 16;
    const uint32_t krowb = (((lid >> 4) << 3) + (lid & 7)) * AT_STRIDE + ((lid >> 3) & 1) * 16;
    const uint32_t vrowb = (lid & 15) * AT_STRIDE + ((lid >> 4) & 1) * 16;

    for (int half_t = 0; half_t < 2; half_t++) {
        const int qt = half_t ? (15 - pr) : pr;       // q-tile of 128 rows
        const __half* QB = g_q16 + ((size_t)bh * Ss + qt * 128) * HD;
        const int nk = 2 * qt + 2;

        // Q tile: 128 rows x 128B
#pragma unroll
        for (int i = 0; i < 4; i++) {
            int idx = tid + i * 256;
            int r = idx >> 3, c = idx & 7;
            cp_async16(sb + r * AT_STRIDE + c * 16, QB + (size_t)r * HD + c * 8);
        }
        cp_commit();
        issue(0, 0);
        if (nk > 1) issue(1, 1);

        float acc[8][4];
#pragma unroll
        for (int i = 0; i < 8; i++)
#pragma unroll
            for (int j = 0; j < 4; j++) acc[i][j] = 0.f;
        float mrow[2] = { -1e30f, -1e30f }, lrow[2] = { 0.f, 0.f };

        int stage = 0;
        for (int kt = 0; kt < nk; kt++) {
            if (kt + 1 < nk) cp_wait<1>(); else cp_wait<0>();
            __syncthreads();          // chunk kt (and Q) ready + old stage reads done
            if (kt + 2 < nk) issue(kt + 2, (kt + 2) % 3);

            const uint32_t kbt = sb + KV0 + stage * KV_STAGE;
            const uint32_t vbt = kbt + KV_TILE;

            // ---- S = q16 @ k16^T  (1 MMA term) ----
            float sf[8][4];
#pragma unroll
            for (int i = 0; i < 8; i++)
#pragma unroll
                for (int j = 0; j < 4; j++) sf[i][j] = 0.f;

#pragma unroll
            for (int kk = 0; kk < 4; kk++) {
                uint32_t aH[4];
                ldsm_x4(aH, sb + qrowb + kk * 32);
#pragma unroll
                for (int nf2 = 0; nf2 < 4; nf2++) {
                    uint32_t rH[4];
                    ldsm_x4(rH, kbt + nf2 * 16 * AT_STRIDE + krowb + kk * 32);
                    mma16816(sf[nf2 * 2],     aH, rH);
                    mma16816(sf[nf2 * 2 + 1], aH, rH + 2);
                }
            }

            if (kt >= 2 * qt) {     // diagonal region: causal mask
                int r0 = wid * 16 + (lid >> 2);
                int coff = kt * 64 - qt * 128;
#pragma unroll
                for (int nf = 0; nf < 8; nf++) {
                    int c0 = coff + nf * 8 + (lid & 3) * 2;
                    if (c0     > r0)     sf[nf][0] = -1e30f;
                    if (c0 + 1 > r0)     sf[nf][1] = -1e30f;
                    if (c0     > r0 + 8) sf[nf][2] = -1e30f;
                    if (c0 + 1 > r0 + 8) sf[nf][3] = -1e30f;
                }
            }

            // ---- online softmax in exp2 domain ----
#pragma unroll
            for (int hf = 0; hf < 2; hf++) {
                float mx = -1e30f;
#pragma unroll
                for (int nf = 0; nf < 8; nf++)
                    mx = fmaxf(mx, fmaxf(sf[nf][hf * 2], sf[nf][hf * 2 + 1]));
                mx = fmaxf(mx, __shfl_xor_sync(0xffffffffu, mx, 1));
                mx = fmaxf(mx, __shfl_xor_sync(0xffffffffu, mx, 2));
                float mnew = fmaxf(mrow[hf], mx);
                float alpha = ex2(mrow[hf] - mnew);
                mrow[hf] = mnew;
                float sum = 0.f;
#pragma unroll
                for (int nf = 0; nf < 8; nf++) {
                    sf[nf][hf * 2]     = ex2(sf[nf][hf * 2] - mnew);
                    sf[nf][hf * 2 + 1] = ex2(sf[nf][hf * 2 + 1] - mnew);
                    sum += sf[nf][hf * 2] + sf[nf][hf * 2 + 1];
                }
                sum += __shfl_xor_sync(0xffffffffu, sum, 1);
                sum += __shfl_xor_sync(0xffffffffu, sum, 2);
                lrow[hf] = lrow[hf] * alpha + sum;
#pragma unroll
                for (int nf = 0; nf < 8; nf++) {
                    acc[nf][hf * 2]     *= alpha;
                    acc[nf][hf * 2 + 1] *= alpha;
                }
            }

            // ---- O += P16 @ v16  (1 MMA term) ----
#pragma unroll
            for (int kk2 = 0; kk2 < 4; kk2++) {
                uint32_t aPh[4];
#pragma unroll
                for (int q = 0; q < 2; q++) {
                    const float* c = sf[kk2 * 2 + q];
                    aPh[q * 2]     = packh(c[0], c[1]);
                    aPh[q * 2 + 1] = packh(c[2], c[3]);
                }
#pragma unroll
                for (int nf2 = 0; nf2 < 4; nf2++) {
                    uint32_t vH[4];
                    ldsm_x4_t(vH, vbt + (kk2 * 16) * AT_STRIDE + vrowb + nf2 * 32);
                    mma16816(acc[nf2 * 2],     aPh, vH);
                    mma16816(acc[nf2 * 2 + 1], aPh, vH + 2);
                }
            }
            stage = (stage == 2) ? 0 : stage + 1;
        }

        // ---- epilogue: ctx -> single fp16 (B,S,D) ----
        float inv0 = 1.f / lrow[0], inv1 = 1.f / lrow[1];
        int r0 = qt * 128 + wid * 16 + (lid >> 2);
#pragma unroll
        for (int nf = 0; nf < 8; nf++) {
            int d0 = h * HD + nf * 8 + (lid & 3) * 2;
            size_t o0 = ((size_t)b * Ss + r0) * Dd + d0;
            size_t o1 = ((size_t)b * Ss + r0 + 8) * Dd + d0;
            *(__half2*)(g_c16 + o0) =
                __floats2half2_rn(acc[nf][0] * inv0, acc[nf][1] * inv0);
            *(__half2*)(g_c16 + o1) =
                __floats2half2_rn(acc[nf][2] * inv1, acc[nf][3] * inv1);
        }
        __syncthreads();    // all smem reads done before next half's loads
    }
}

// ---------------------------------------------------------------------------
extern "C" void kernel_launch(void* const* d_in, const int* in_sizes, int n_in,
                              void* d_out, int out_size)
{
    const float* x  = (const float*)d_in[0];
    const float* Wq = (const float*)d_in[1];
    const float* bq = (const float*)d_in[2];
    const float* Wk = (const float*)d_in[3];
    const float* bk = (const float*)d_in[4];
    const float* Wv = (const float*)d_in[5];
    const float* bv = (const float*)d_in[6];
    const float* Wo = (const float*)d_in[7];
    const float* bo = (const float*)d_in[8];
    float* out = (float*)d_out;

    cudaFuncSetAttribute(gemm_qkv, cudaFuncAttributeMaxDynamicSharedMemorySize, GEMM_SMEM);
    cudaFuncSetAttribute(gemm_out, cudaFuncAttributeMaxDynamicSharedMemorySize, GEMM_SMEM);
    cudaFuncSetAttribute(attn_mma, cudaFuncAttributeMaxDynamicSharedMemorySize, ATTN_SMEM);

    split_all<<<(Mtot * Dd + 4 * Dd * Dd) / 4096, 256>>>(x, Wq, Wk, Wv, Wo);

    gemm_qkv<<<dim3(Dd / 128, Mtot / 128, 3), 128, GEMM_SMEM>>>(bq, bk, bv);

    attn_mma<<<dim3(8, Bb * Hh), 256, ATTN_SMEM>>>();

    gemm_out<<<dim3(Dd / 128, Mtot / 128), 128, GEMM_SMEM>>>(bo, out);
}